// round 5
// baseline (speedup 1.0000x reference)
#include <cuda_runtime.h>
#include <cuda_bf16.h>

#define BB 8
#define NN 512
#define DD 64

typedef unsigned int u32;
typedef unsigned short u16;

// ---- dynamic smem layout (offsets from 1KB-aligned base) ----
#define OFF_AP_HI 0        // A' hi: [2 q][64 h][128B row]
#define OFF_AP_LO 16384
#define OFF_XH    32768    // X tile hi: [128 k][128B row]
#define OFF_XL    49152
#define OFF_SCH   65536    // scores hi: [16 rows][256B] (rows 0,1 valid)
#define OFF_SCL   69632
#define OFF_BIAS  73728    // 2*64 f32 (hq+b1)
#define OFF_W2    74240    // 64 f32
#define OFF_VM    74496    // 128 f32
#define SMEM_DYN  (75008 + 1024)

#define SWZ(o)   ((o) ^ (((o) >> 3) & 0x70))   // 128B-row swizzle
#define SCSWZ(o) ((o) ^ (((o) >> 4) & 0x70))   // 256B-row swizzle (scores)

static __device__ __forceinline__ u32 smem_u32(const void* p) {
    u32 a;
    asm("{ .reg .u64 t; cvta.to.shared.u64 t, %1; cvt.u32.u64 %0, t; }" : "=r"(a) : "l"(p));
    return a;
}
static __device__ __forceinline__ void ldsm_x4(u32* r, u32 addr) {
    asm volatile("ldmatrix.sync.aligned.m8n8.x4.shared.b16 {%0,%1,%2,%3}, [%4];"
        : "=r"(r[0]), "=r"(r[1]), "=r"(r[2]), "=r"(r[3]) : "r"(addr));
}
static __device__ __forceinline__ void ldsm_x2(u32* r, u32 addr) {
    asm volatile("ldmatrix.sync.aligned.m8n8.x2.shared.b16 {%0,%1}, [%2];"
        : "=r"(r[0]), "=r"(r[1]) : "r"(addr));
}
static __device__ __forceinline__ void ldsm_x2t(u32* r, u32 addr) {
    asm volatile("ldmatrix.sync.aligned.m8n8.x2.trans.shared.b16 {%0,%1}, [%2];"
        : "=r"(r[0]), "=r"(r[1]) : "r"(addr));
}
static __device__ __forceinline__ void mma_bf16(float* c, const u32* a, const u32* b) {
    asm volatile("mma.sync.aligned.m16n8k16.row.col.f32.bf16.bf16.f32 "
        "{%0,%1,%2,%3}, {%4,%5,%6,%7}, {%8,%9}, {%0,%1,%2,%3};"
        : "+f"(c[0]), "+f"(c[1]), "+f"(c[2]), "+f"(c[3])
        : "r"(a[0]), "r"(a[1]), "r"(a[2]), "r"(a[3]), "r"(b[0]), "r"(b[1]));
}
static __device__ __forceinline__ void split2(float a0, float a1, u32& hp, u32& lp) {
    __nv_bfloat16 h0 = __float2bfloat16(a0), h1 = __float2bfloat16(a1);
    __nv_bfloat16 l0 = __float2bfloat16(a0 - __bfloat162float(h0));
    __nv_bfloat16 l1 = __float2bfloat16(a1 - __bfloat162float(h1));
    hp = (u32)__bfloat16_as_ushort(h0) | ((u32)__bfloat16_as_ushort(h1) << 16);
    lp = (u32)__bfloat16_as_ushort(l0) | ((u32)__bfloat16_as_ushort(l1) << 16);
}
static __device__ __forceinline__ void store_score(char* sm, int row, int kc, float v) {
    __nv_bfloat16 h = __float2bfloat16(v);
    __nv_bfloat16 l = __float2bfloat16(v - __bfloat162float(h));
    u32 o = SCSWZ((u32)(row * 256 + kc * 2));
    *(u16*)(sm + OFF_SCH + o) = __bfloat16_as_ushort(h);
    *(u16*)(sm + OFF_SCL + o) = __bfloat16_as_ushort(l);
}

// ---------------------------------------------------------------------------
// One CTA = (b, queries qb, qb+1). 8 warps.
// Warp w: query qs=w>>2, key-slice msl=w&3 (32 keys of the 128-key tile).
//   S[key, h] = X_k · A'_q^T via mma.sync bf16 (3-term hi/lo split)
//   epilogue: +bias, PReLU, *W2, quad-reduce -> masked scores (bf16 hi/lo)
//   encoded += scores · X via a second mma (warp owns an 8-d column slice)
// ---------------------------------------------------------------------------
__global__ __launch_bounds__(256, 2) void din_mma(
    const float* __restrict__ X, const float* __restrict__ VM,
    const float* __restrict__ W1, const float* __restrict__ B1,
    const float* __restrict__ PA, const float* __restrict__ W2,
    const float* __restrict__ B2, float* __restrict__ OUT)
{
    extern __shared__ char smraw[];
    const u32 sm_raw = smem_u32(smraw);
    const u32 smb = (sm_raw + 1023) & ~1023u;
    char* sm = smraw + (smb - sm_raw);

    const int tid = threadIdx.x, wid = tid >> 5, lid = tid & 31;
    const int qs_w = wid >> 2, msl = wid & 3;
    const int b = blockIdx.x & 7, g = blockIdx.x >> 3;
    const int qb = 2 * (255 - g);              // long queries first
    const int q_w = qb + qs_w;
    const int nt = ((qb + 1) >> 7) + 1;
    const float* Xb = X + b * NN * DD;

    // ---- one-time: stage A' = Wm .* x_q + (Wk - Wd), split bf16 hi/lo ----
    for (int p = tid; p < 4096; p += 256) {
        int qs = p >> 11, r = (p >> 5) & 63, dp = p & 31, d = dp * 2;
        const float* w1r = W1 + r * 256;
        float x0 = __ldg(Xb + (qb + qs) * DD + d);
        float x1 = __ldg(Xb + (qb + qs) * DD + d + 1);
        float a0 = fmaf(__ldg(w1r + 192 + d),     x0, __ldg(w1r + 64 + d)     - __ldg(w1r + 128 + d));
        float a1 = fmaf(__ldg(w1r + 192 + d + 1), x1, __ldg(w1r + 64 + d + 1) - __ldg(w1r + 128 + d + 1));
        u32 hp, lp; split2(a0, a1, hp, lp);
        u32 o = SWZ((u32)(r * 128 + dp * 4));
        *(u32*)(sm + OFF_AP_HI + qs * 8192 + o) = hp;
        *(u32*)(sm + OFF_AP_LO + qs * 8192 + o) = lp;
    }
    // ---- bias[qs][h] = hq + b1 ----
    if (tid < 128) {
        int qs = tid >> 6, h = tid & 63;
        const float* w1r = W1 + h * 256;
        const float* xr  = Xb + (qb + qs) * DD;
        float acc = __ldg(B1 + h);
        #pragma unroll 8
        for (int d = 0; d < 64; d++)
            acc = fmaf(__ldg(w1r + d) + __ldg(w1r + 128 + d), __ldg(xr + d), acc);
        ((float*)(sm + OFF_BIAS))[tid] = acc;
    }
    if (tid < 64) ((float*)(sm + OFF_W2))[tid] = __ldg(W2 + tid);

    const float aslope = __ldg(PA);
    const float b2v    = __ldg(B2);

    float ec[4] = {0.f, 0.f, 0.f, 0.f};   // encoded c-frag (rows 0,1 valid)

    #pragma unroll 1
    for (int t = 0; t < nt; t++) {
        const int k0 = t << 7;
        __syncthreads();                   // prev tile fully consumed
        // ---- stage X tile (hi/lo split) + VM ----
        for (int p = tid; p < 4096; p += 256) {
            int k = p >> 5, dp = p & 31;
            float2 v = __ldg((const float2*)(Xb + (k0 + k) * DD + dp * 2));
            u32 hp, lp; split2(v.x, v.y, hp, lp);
            u32 o = SWZ((u32)(k * 128 + dp * 4));
            *(u32*)(sm + OFF_XH + o) = hp;
            *(u32*)(sm + OFF_XL + o) = lp;
        }
        if (tid < 128) ((float*)(sm + OFF_VM))[tid] = __ldg(VM + b * NN + k0 + tid);
        __syncthreads();

        // ================= S phase =================
        const int km0 = k0 + msl * 32;
        if (km0 <= q_w) {
            #pragma unroll 1
            for (int mi = 0; mi < 2; mi++) {
                const int kmrel = msl * 32 + mi * 16;    // key row within tile
                u32 a[2][4][4];
                {
                    int arow  = kmrel + (lid & 15);
                    int acolb = (lid >> 4) * 16;
                    #pragma unroll
                    for (int ks = 0; ks < 4; ks++) {
                        u32 o = SWZ((u32)(arow * 128 + ks * 32 + acolb));
                        ldsm_x4(a[0][ks], smb + OFF_XH + o);
                        ldsm_x4(a[1][ks], smb + OFF_XL + o);
                    }
                }
                float sum0 = 0.f, sum1 = 0.f;
                const int hc = 2 * (lid & 3);
                #pragma unroll
                for (int n = 0; n < 8; n++) {
                    float c[4] = {0.f, 0.f, 0.f, 0.f};
                    int brow  = n * 8 + (lid & 7);
                    int bcolb = ((lid >> 3) & 1) * 16;
                    #pragma unroll
                    for (int ks = 0; ks < 4; ks++) {
                        u32 bo = SWZ((u32)(brow * 128 + ks * 32 + bcolb));
                        u32 bh[2], bl[2];
                        ldsm_x2(bh, smb + OFF_AP_HI + qs_w * 8192 + bo);
                        ldsm_x2(bl, smb + OFF_AP_LO + qs_w * 8192 + bo);
                        mma_bf16(c, a[0][ks], bh);   // hi*hi
                        mma_bf16(c, a[0][ks], bl);   // hi*lo
                        mma_bf16(c, a[1][ks], bh);   // lo*hi
                    }
                    float2 bias2 = *(const float2*)(sm + OFF_BIAS + (qs_w * 64 + n * 8 + hc) * 4);
                    float2 w22   = *(const float2*)(sm + OFF_W2 + (n * 8 + hc) * 4);
                    float s0 = c[0] + bias2.x, s1 = c[1] + bias2.y;
                    float s2 = c[2] + bias2.x, s3 = c[3] + bias2.y;
                    float p0 = fmaxf(s0, 0.f) + aslope * fminf(s0, 0.f);
                    float p1 = fmaxf(s1, 0.f) + aslope * fminf(s1, 0.f);
                    float p2 = fmaxf(s2, 0.f) + aslope * fminf(s2, 0.f);
                    float p3 = fmaxf(s3, 0.f) + aslope * fminf(s3, 0.f);
                    sum0 = fmaf(p0, w22.x, fmaf(p1, w22.y, sum0));
                    sum1 = fmaf(p2, w22.x, fmaf(p3, w22.y, sum1));
                }
                sum0 += __shfl_xor_sync(0xffffffffu, sum0, 1);
                sum0 += __shfl_xor_sync(0xffffffffu, sum0, 2);
                sum1 += __shfl_xor_sync(0xffffffffu, sum1, 1);
                sum1 += __shfl_xor_sync(0xffffffffu, sum1, 2);
                if ((lid & 3) == 0) {
                    int kc = kmrel + (lid >> 2);
                    const float* vmp = (const float*)(sm + OFF_VM);
                    float v0 = (k0 + kc     <= q_w) ? (sum0 + b2v) * vmp[kc]     : 0.f;
                    float v1 = (k0 + kc + 8 <= q_w) ? (sum1 + b2v) * vmp[kc + 8] : 0.f;
                    store_score(sm, qs_w, kc,     v0);
                    store_score(sm, qs_w, kc + 8, v1);
                }
            }
        } else {
            store_score(sm, qs_w, msl * 32 + lid, 0.f);   // zero this slice
        }
        __syncthreads();

        // ================= encoded mma: ec += scores · X =================
        {
            const int srow  = lid & 15;
            const int scolb = (lid >> 4) * 16;
            #pragma unroll
            for (int kt = 0; kt < 8; kt++) {
                u32 so = SCSWZ((u32)(srow * 256 + kt * 32 + scolb));
                u32 ash[4], asl[4];
                ldsm_x4(ash, smb + OFF_SCH + so);
                ldsm_x4(asl, smb + OFF_SCL + so);
                u32 xo = SWZ((u32)((kt * 16 + (lid & 15)) * 128 + wid * 16));
                u32 bxh[2], bxl[2];
                ldsm_x2t(bxh, smb + OFF_XH + xo);
                ldsm_x2t(bxl, smb + OFF_XL + xo);
                mma_bf16(ec, ash, bxh);
                mma_bf16(ec, ash, bxl);
                mma_bf16(ec, asl, bxh);
            }
        }
    }

    // ---- output: lanes 0-7 hold rows 0,1 of warp's 8-d column slice ----
    if (lid < 8) {
        int qsr = lid >> 2, d0 = wid * 8 + 2 * (lid & 3);
        *(float2*)(OUT + (b * NN + qb + qsr) * DD + d0) = make_float2(ec[0], ec[1]);
    }
}

// ---------------------------------------------------------------------------
// Inputs (metadata order):
//  0 past_lengths (unused)  1 user_embeddings [8,512,64] f32  2 valid_mask [8,512]
//  3 W1 [64,256]  4 b1 [64]  5 prelu_a [1]  6 W2 [1,64]  7 b2 [1]
// Output: encoded [8,512,64] f32
// ---------------------------------------------------------------------------
extern "C" void kernel_launch(void* const* d_in, const int* in_sizes, int n_in,
                              void* d_out, int out_size)
{
    const float* X  = (const float*)d_in[1];
    const float* VM = (const float*)d_in[2];
    const float* W1 = (const float*)d_in[3];
    const float* b1 = (const float*)d_in[4];
    const float* pa = (const float*)d_in[5];
    const float* W2 = (const float*)d_in[6];
    const float* b2 = (const float*)d_in[7];
    float* OUT = (float*)d_out;

    static int attr_set = 0;
    if (!attr_set) {
        cudaFuncSetAttribute(din_mma, cudaFuncAttributeMaxDynamicSharedMemorySize, SMEM_DYN);
        attr_set = 1;
    }
    din_mma<<<BB * NN / 2, 256, SMEM_DYN>>>(X, VM, W1, b1, pa, W2, b2, OUT);
}

// round 6
// speedup vs baseline: 1.0754x; 1.0754x over previous
#include <cuda_runtime.h>
#include <cuda_bf16.h>

#define BB 8
#define NN 512
#define DD 64

typedef unsigned int u32;
typedef unsigned short u16;

#define SWZ(o)   ((o) ^ (((o) >> 3) & 0x70))   // 128B-row swizzle
#define SCSWZ(o) ((o) ^ (((o) >> 4) & 0x70))   // 256B-row swizzle (scores)

static __device__ __forceinline__ u32 smem_u32(const void* p) {
    u32 a;
    asm("{ .reg .u64 t; cvta.to.shared.u64 t, %1; cvt.u32.u64 %0, t; }" : "=r"(a) : "l"(p));
    return a;
}
static __device__ __forceinline__ void ldsm_x4(u32* r, u32 addr) {
    asm volatile("ldmatrix.sync.aligned.m8n8.x4.shared.b16 {%0,%1,%2,%3}, [%4];"
        : "=r"(r[0]), "=r"(r[1]), "=r"(r[2]), "=r"(r[3]) : "r"(addr));
}
static __device__ __forceinline__ void ldsm_x2(u32* r, u32 addr) {
    asm volatile("ldmatrix.sync.aligned.m8n8.x2.shared.b16 {%0,%1}, [%2];"
        : "=r"(r[0]), "=r"(r[1]) : "r"(addr));
}
static __device__ __forceinline__ void ldsm_x2t(u32* r, u32 addr) {
    asm volatile("ldmatrix.sync.aligned.m8n8.x2.trans.shared.b16 {%0,%1}, [%2];"
        : "=r"(r[0]), "=r"(r[1]) : "r"(addr));
}
static __device__ __forceinline__ void mma_bf16(float* c, const u32* a, const u32* b) {
    asm volatile("mma.sync.aligned.m16n8k16.row.col.f32.bf16.bf16.f32 "
        "{%0,%1,%2,%3}, {%4,%5,%6,%7}, {%8,%9}, {%0,%1,%2,%3};"
        : "+f"(c[0]), "+f"(c[1]), "+f"(c[2]), "+f"(c[3])
        : "r"(a[0]), "r"(a[1]), "r"(a[2]), "r"(a[3]), "r"(b[0]), "r"(b[1]));
}
static __device__ __forceinline__ void split2(float a0, float a1, u32& hp, u32& lp) {
    __nv_bfloat16 h0 = __float2bfloat16(a0), h1 = __float2bfloat16(a1);
    __nv_bfloat16 l0 = __float2bfloat16(a0 - __bfloat162float(h0));
    __nv_bfloat16 l1 = __float2bfloat16(a1 - __bfloat162float(h1));
    hp = (u32)__bfloat16_as_ushort(h0) | ((u32)__bfloat16_as_ushort(h1) << 16);
    lp = (u32)__bfloat16_as_ushort(l0) | ((u32)__bfloat16_as_ushort(l1) << 16);
}

// ---------------------------------------------------------------------------
// One CTA = (b, queries qb..qb+3). 8 warps = 4 queries x 2 h-halves.
// Warp holds its A'(q, 32h) mma B-fragments in 64 REGISTERS for the whole
// kernel (loaded once via ldmatrix from a transient staging pass).
//   S[k, h] = X_k . A'^T: per 16-key slab: 8 A-ldmatrix + 48 mma, zero B loads
//   epilogue: +bias(hq+b1), PReLU, *W2, quad-reduce -> h-half partials in smem
//   scores (masked, +b2, bf16 hi/lo) -> encoded += scores . X via second mma
// ---------------------------------------------------------------------------
__global__ __launch_bounds__(256, 1) void din_mma(
    const float* __restrict__ X, const float* __restrict__ VM,
    const float* __restrict__ W1, const float* __restrict__ B1,
    const float* __restrict__ PA, const float* __restrict__ W2,
    const float* __restrict__ B2, float* __restrict__ OUT)
{
    __shared__ __align__(128) char sm_xh[16384];   // X tile hi [128k][128B]
    __shared__ __align__(128) char sm_xl[16384];   // X tile lo
    __shared__ __align__(128) char sm_sch[4096];   // scores hi [16][256B]
    __shared__ __align__(128) char sm_scl[4096];   // scores lo
    __shared__ float sm_part[4 * 128 * 2];         // h-half partial scores
    __shared__ float sm_bias[4 * 64];              // hq + b1
    __shared__ float sm_w2[64];
    __shared__ float sm_vm[128];

    const u32 xh_b  = smem_u32(sm_xh);
    const u32 xl_b  = smem_u32(sm_xl);
    const u32 sch_b = smem_u32(sm_sch);
    const u32 scl_b = smem_u32(sm_scl);

    const int tid = threadIdx.x, wid = tid >> 5, lid = tid & 31;
    const int q_w = wid >> 1, hh = wid & 1;        // warp's query / h-half
    const int b = blockIdx.x & 7, g = blockIdx.x >> 3;
    const int qb = 4 * (127 - g);                  // long queries first
    const int q_mine = qb + q_w;
    const int nt = ((qb + 3) >> 7) + 1;
    const float* Xb = X + b * NN * DD;

    // ---- zero score buffers (rows 4-15 stay zero forever) ----
    for (int p = tid; p < 1024; p += 256) {
        ((u32*)sm_sch)[p] = 0; ((u32*)sm_scl)[p] = 0;
    }
    // ---- bias[q][h] = hq + b1 ----
    {
        int q = tid >> 6, h = tid & 63;
        const float* w1r = W1 + h * 256;
        const float* xr  = Xb + (qb + q) * DD;
        float acc = __ldg(B1 + h);
        #pragma unroll 8
        for (int d = 0; d < 64; d++)
            acc = fmaf(__ldg(w1r + d) + __ldg(w1r + 128 + d), __ldg(xr + d), acc);
        sm_bias[tid] = acc;
    }
    if (tid < 64) sm_w2[tid] = __ldg(W2 + tid);

    // ---- A' = Wm .* x_q + (Wk - Wd): stage 2 queries at a time into the X
    //      buffers, load each warp's B fragments into registers, move on ----
    u32 bh[4][4][2], bl[4][4][2];
    #pragma unroll 1
    for (int pass = 0; pass < 2; pass++) {
        __syncthreads();
        for (int p = tid; p < 4096; p += 256) {
            int r = p >> 5, dp = p & 31, d = dp * 2;
            int q = qb + 2 * pass + (r >> 6);
            const float* w1r = W1 + (r & 63) * 256;
            float x0 = __ldg(Xb + q * DD + d), x1 = __ldg(Xb + q * DD + d + 1);
            float a0 = fmaf(__ldg(w1r + 192 + d),     x0, __ldg(w1r + 64 + d)     - __ldg(w1r + 128 + d));
            float a1 = fmaf(__ldg(w1r + 192 + d + 1), x1, __ldg(w1r + 64 + d + 1) - __ldg(w1r + 128 + d + 1));
            u32 hp, lp; split2(a0, a1, hp, lp);
            u32 o = SWZ((u32)(r * 128 + dp * 4));
            *(u32*)(sm_xh + o) = hp;
            *(u32*)(sm_xl + o) = lp;
        }
        __syncthreads();
        if ((q_w >> 1) == pass) {
            int rbase = (q_w & 1) * 64 + hh * 32;
            #pragma unroll
            for (int nb = 0; nb < 4; nb++)
                #pragma unroll
                for (int ks = 0; ks < 4; ks++) {
                    u32 o = SWZ((u32)((rbase + nb * 8 + (lid & 7)) * 128
                                      + ks * 32 + ((lid >> 3) & 1) * 16));
                    ldsm_x2(bh[nb][ks], xh_b + o);
                    ldsm_x2(bl[nb][ks], xl_b + o);
                }
        }
    }

    const float aslope = __ldg(PA);
    const float b2v    = __ldg(B2);
    float ec[4] = {0.f, 0.f, 0.f, 0.f};           // encoded c-frag

    #pragma unroll 1
    for (int t = 0; t < nt; t++) {
        const int k0 = t << 7;
        __syncthreads();                           // prev tile fully consumed
        // ---- stage X tile (hi/lo split) + VM ----
        for (int p = tid; p < 4096; p += 256) {
            int k = p >> 5, dp = p & 31;
            float2 v = __ldg((const float2*)(Xb + (k0 + k) * DD + dp * 2));
            u32 hp, lp; split2(v.x, v.y, hp, lp);
            u32 o = SWZ((u32)(k * 128 + dp * 4));
            *(u32*)(sm_xh + o) = hp;
            *(u32*)(sm_xl + o) = lp;
        }
        if (tid < 128) sm_vm[tid] = __ldg(VM + b * NN + k0 + tid);
        __syncthreads();

        // ================= S phase: warp = (q_w, 32 h of half hh) ==========
        const int mi_hi = (k0 <= q_mine) ? min(8, ((q_mine - k0) >> 4) + 1) : 0;
        #pragma unroll 1
        for (int mi = 0; mi < mi_hi; mi++) {
            u32 ah[4][4], al[4][4];
            {
                int arow  = mi * 16 + (lid & 15);
                int acolb = (lid >> 4) * 16;
                #pragma unroll
                for (int ks = 0; ks < 4; ks++) {
                    u32 o = SWZ((u32)(arow * 128 + ks * 32 + acolb));
                    ldsm_x4(ah[ks], xh_b + o);
                    ldsm_x4(al[ks], xl_b + o);
                }
            }
            float c[4][4];
            #pragma unroll
            for (int nb = 0; nb < 4; nb++)
                #pragma unroll
                for (int i = 0; i < 4; i++) c[nb][i] = 0.f;
            #pragma unroll
            for (int nb = 0; nb < 4; nb++)
                #pragma unroll
                for (int ks = 0; ks < 4; ks++) {
                    mma_bf16(c[nb], ah[ks], bh[nb][ks]);   // hi*hi
                    mma_bf16(c[nb], ah[ks], bl[nb][ks]);   // hi*lo
                    mma_bf16(c[nb], al[ks], bh[nb][ks]);   // lo*hi
                }
            float s0 = 0.f, s8 = 0.f;
            #pragma unroll
            for (int nb = 0; nb < 4; nb++) {
                int hcol = hh * 32 + nb * 8 + 2 * (lid & 3);
                float2 bias2 = *(const float2*)(sm_bias + q_w * 64 + hcol);
                float2 w22   = *(const float2*)(sm_w2 + hcol);
                float v0 = c[nb][0] + bias2.x, v1 = c[nb][1] + bias2.y;
                float v2 = c[nb][2] + bias2.x, v3 = c[nb][3] + bias2.y;
                float p0 = fmaxf(v0, 0.f) + aslope * fminf(v0, 0.f);
                float p1 = fmaxf(v1, 0.f) + aslope * fminf(v1, 0.f);
                float p2 = fmaxf(v2, 0.f) + aslope * fminf(v2, 0.f);
                float p3 = fmaxf(v3, 0.f) + aslope * fminf(v3, 0.f);
                s0 = fmaf(p0, w22.x, fmaf(p1, w22.y, s0));
                s8 = fmaf(p2, w22.x, fmaf(p3, w22.y, s8));
            }
            s0 += __shfl_xor_sync(0xffffffffu, s0, 1);
            s0 += __shfl_xor_sync(0xffffffffu, s0, 2);
            s8 += __shfl_xor_sync(0xffffffffu, s8, 1);
            s8 += __shfl_xor_sync(0xffffffffu, s8, 2);
            if ((lid & 3) == 0) {
                int kr = mi * 16 + (lid >> 2);
                sm_part[(q_w * 128 + kr) * 2 + hh]     = s0;
                sm_part[(q_w * 128 + kr + 8) * 2 + hh] = s8;
            }
        }
        for (int mi = mi_hi; mi < 8; mi++)
            if (lid < 16) sm_part[(q_w * 128 + mi * 16 + lid) * 2 + hh] = 0.f;
        __syncthreads();

        // ---- combine h-halves -> masked scores, split bf16 hi/lo ----
        for (int p = tid; p < 512; p += 256) {
            int q = p >> 7, kk = p & 127;
            float cm = (k0 + kk <= qb + q) ? sm_vm[kk] : 0.f;
            float s = (sm_part[(q * 128 + kk) * 2] + sm_part[(q * 128 + kk) * 2 + 1]
                       + b2v) * cm;
            __nv_bfloat16 h = __float2bfloat16(s);
            __nv_bfloat16 l = __float2bfloat16(s - __bfloat162float(h));
            u32 o = SCSWZ((u32)(q * 256 + kk * 2));
            *(u16*)(sm_sch + o) = __bfloat16_as_ushort(h);
            *(u16*)(sm_scl + o) = __bfloat16_as_ushort(l);
        }
        __syncthreads();

        // ================= encoded mma: ec += scores . X ===================
        {
            const int srow = lid & 15, scolb = (lid >> 4) * 16;
            #pragma unroll
            for (int kt = 0; kt < 8; kt++) {
                u32 so = SCSWZ((u32)(srow * 256 + kt * 32 + scolb));
                u32 ash[4], asl[4];
                ldsm_x4(ash, sch_b + so);
                ldsm_x4(asl, scl_b + so);
                u32 xo = SWZ((u32)((kt * 16 + (lid & 15)) * 128 + wid * 16));
                u32 bxh[2], bxl[2];
                ldsm_x2t(bxh, xh_b + xo);
                ldsm_x2t(bxl, xl_b + xo);
                mma_bf16(ec, ash, bxh);
                mma_bf16(ec, ash, bxl);
                mma_bf16(ec, asl, bxh);
            }
        }
    }

    // ---- output: rows 0-3 of ec (lanes 0-15, c0/c1) ----
    if (lid < 16) {
        int q = lid >> 2, d0 = wid * 8 + 2 * (lid & 3);
        *(float2*)(OUT + (b * NN + qb + q) * DD + d0) = make_float2(ec[0], ec[1]);
    }
}

// ---------------------------------------------------------------------------
// Inputs (metadata order):
//  0 past_lengths (unused)  1 user_embeddings [8,512,64] f32  2 valid_mask [8,512]
//  3 W1 [64,256]  4 b1 [64]  5 prelu_a [1]  6 W2 [1,64]  7 b2 [1]
// Output: encoded [8,512,64] f32
// ---------------------------------------------------------------------------
extern "C" void kernel_launch(void* const* d_in, const int* in_sizes, int n_in,
                              void* d_out, int out_size)
{
    const float* X  = (const float*)d_in[1];
    const float* VM = (const float*)d_in[2];
    const float* W1 = (const float*)d_in[3];
    const float* b1 = (const float*)d_in[4];
    const float* pa = (const float*)d_in[5];
    const float* W2 = (const float*)d_in[6];
    const float* b2 = (const float*)d_in[7];
    float* OUT = (float*)d_out;

    din_mma<<<BB * NN / 4, 256>>>(X, VM, W1, b1, pa, W2, b2, OUT);
}

// round 7
// speedup vs baseline: 2.1266x; 1.9775x over previous
#include <cuda_runtime.h>
#include <cuda_bf16.h>

#define BB 8
#define NN 512
#define DD 64

typedef unsigned int u32;
typedef unsigned short u16;

#define SWZ(o)   ((o) ^ (((o) >> 3) & 0x70))   // 128B-row swizzle
#define SCSWZ(o) ((o) ^ (((o) >> 4) & 0x70))   // 256B-row swizzle (scores)

// global scratch: X split into bf16 hi/lo, swizzled tile-ready layout
__device__ char  g_xh[BB * 4 * 16384];   // [b][tile][SWZ(row*128+dp*4)]
__device__ char  g_xl[BB * 4 * 16384];
__device__ float g_hq[BB * NN * 64];     // hq + b1

// ---- dynamic smem offsets ----
#define OXH(buf) ((buf) * 32768)
#define OXL(buf) ((buf) * 32768 + 16384)
#define OSCH  65536
#define OSCL  69632
#define OPART 73728
#define OBIAS 77824
#define OW2   78848
#define SMEM_DYN 79104

static __device__ __forceinline__ u32 smem_u32(const void* p) {
    u32 a;
    asm("{ .reg .u64 t; cvta.to.shared.u64 t, %1; cvt.u32.u64 %0, t; }" : "=r"(a) : "l"(p));
    return a;
}
static __device__ __forceinline__ void ldsm_x4(u32* r, u32 addr) {
    asm volatile("ldmatrix.sync.aligned.m8n8.x4.shared.b16 {%0,%1,%2,%3}, [%4];"
        : "=r"(r[0]), "=r"(r[1]), "=r"(r[2]), "=r"(r[3]) : "r"(addr));
}
static __device__ __forceinline__ void ldsm_x2(u32* r, u32 addr) {
    asm volatile("ldmatrix.sync.aligned.m8n8.x2.shared.b16 {%0,%1}, [%2];"
        : "=r"(r[0]), "=r"(r[1]) : "r"(addr));
}
static __device__ __forceinline__ void ldsm_x2t(u32* r, u32 addr) {
    asm volatile("ldmatrix.sync.aligned.m8n8.x2.trans.shared.b16 {%0,%1}, [%2];"
        : "=r"(r[0]), "=r"(r[1]) : "r"(addr));
}
static __device__ __forceinline__ void mma_bf16(float* c, const u32* a, const u32* b) {
    asm volatile("mma.sync.aligned.m16n8k16.row.col.f32.bf16.bf16.f32 "
        "{%0,%1,%2,%3}, {%4,%5,%6,%7}, {%8,%9}, {%0,%1,%2,%3};"
        : "+f"(c[0]), "+f"(c[1]), "+f"(c[2]), "+f"(c[3])
        : "r"(a[0]), "r"(a[1]), "r"(a[2]), "r"(a[3]), "r"(b[0]), "r"(b[1]));
}
static __device__ __forceinline__ void split2(float a0, float a1, u32& hp, u32& lp) {
    __nv_bfloat16 h0 = __float2bfloat16(a0), h1 = __float2bfloat16(a1);
    __nv_bfloat16 l0 = __float2bfloat16(a0 - __bfloat162float(h0));
    __nv_bfloat16 l1 = __float2bfloat16(a1 - __bfloat162float(h1));
    hp = (u32)__bfloat16_as_ushort(h0) | ((u32)__bfloat16_as_ushort(h1) << 16);
    lp = (u32)__bfloat16_as_ushort(l0) | ((u32)__bfloat16_as_ushort(l1) << 16);
}
static __device__ __forceinline__ void cpasync16(u32 saddr, const void* gptr) {
    asm volatile("{ .reg .u64 g; cvta.to.global.u64 g, %1; "
                 "cp.async.ca.shared.global [%0], [g], 16; }"
                 :: "r"(saddr), "l"(gptr));
}
#define CP_COMMIT() asm volatile("cp.async.commit_group;" ::: "memory")
#define CP_WAIT1()  asm volatile("cp.async.wait_group 1;" ::: "memory")

// ---------------------------------------------------------------------------
// Prep 1: split X into bf16 hi/lo with the tile swizzle baked in.
// ---------------------------------------------------------------------------
__global__ __launch_bounds__(256) void xsplit(const float* __restrict__ X) {
    const int b = blockIdx.x >> 2, t = blockIdx.x & 3, tid = threadIdx.x;
    const float* src = X + (b * NN + t * 128) * DD;
    char* dh = g_xh + b * 65536 + t * 16384;
    char* dl = g_xl + b * 65536 + t * 16384;
    #pragma unroll 4
    for (int p = tid; p < 4096; p += 256) {
        int r = p >> 5, dp = p & 31;
        float2 v = __ldg((const float2*)(src + r * DD + dp * 2));
        u32 hp, lp; split2(v.x, v.y, hp, lp);
        u32 o = SWZ((u32)(r * 128 + dp * 4));
        *(u32*)(dh + o) = hp;
        *(u32*)(dl + o) = lp;
    }
}

// ---------------------------------------------------------------------------
// Prep 2: hq[b,n,h] = x . (Wq + Wd)[h,:] + b1[h]
// ---------------------------------------------------------------------------
__global__ __launch_bounds__(64) void precompute_hq(
    const float* __restrict__ X, const float* __restrict__ W1,
    const float* __restrict__ B1)
{
    __shared__ float sx[16 * DD];
    const int t = threadIdx.x, b = blockIdx.x >> 5, n0 = (blockIdx.x & 31) * 16;
    for (int i = t; i < 256; i += 64)
        reinterpret_cast<float4*>(sx)[i] =
            reinterpret_cast<const float4*>(X + (b * NN + n0) * DD)[i];
    __syncthreads();
    const float bb = __ldg(B1 + t);
    const float4* w1row = reinterpret_cast<const float4*>(W1 + t * 256);
    float4 w[16];
    #pragma unroll
    for (int j = 0; j < 16; j++) {
        float4 wq = __ldg(&w1row[j]);
        float4 wd = __ldg(&w1row[32 + j]);
        w[j] = make_float4(wq.x + wd.x, wq.y + wd.y, wq.z + wd.z, wq.w + wd.w);
    }
    for (int nn = 0; nn < 16; nn++) {
        const float4* xr = reinterpret_cast<const float4*>(sx + nn * DD);
        float s = 0.f;
        #pragma unroll
        for (int j = 0; j < 16; j++) {
            float4 xv = xr[j];
            s += w[j].x * xv.x + w[j].y * xv.y + w[j].z * xv.z + w[j].w * xv.w;
        }
        g_hq[(b * NN + n0 + nn) * 64 + t] = s + bb;
    }
}

// ---------------------------------------------------------------------------
// Main. One CTA = (b, queries qb..qb+3). 8 warps = 4 q x 2 h-halves.
// A'(q,32h) mma B-frags live in registers; X tiles cp.async double-buffered
// from the pre-split global layout.
// ---------------------------------------------------------------------------
__global__ __launch_bounds__(256, 1) void din_mma(
    const float* __restrict__ X, const float* __restrict__ VM,
    const float* __restrict__ W1, const float* __restrict__ PA,
    const float* __restrict__ W2, const float* __restrict__ B2,
    float* __restrict__ OUT)
{
    extern __shared__ __align__(128) char sm[];
    const u32 smb = smem_u32(sm);

    const int tid = threadIdx.x, wid = tid >> 5, lid = tid & 31;
    const int q_w = wid >> 1, hh = wid & 1;
    const int b = blockIdx.x & 7, g = blockIdx.x >> 3;
    const int qb = 4 * (127 - g);              // long queries first
    const int q_mine = qb + q_w;
    const int nt = ((qb + 3) >> 7) + 1;
    const float* Xb = X + b * NN * DD;
    float* part = (float*)(sm + OPART);

    // zero score buffers (rows 4-15 stay zero forever)
    for (int p = tid; p < 2048; p += 256) ((u32*)(sm + OSCH))[p] = 0;
    // bias from precomputed hq
    ((float*)(sm + OBIAS))[tid] = g_hq[(b * NN + qb + (tid >> 6)) * 64 + (tid & 63)];
    if (tid < 64) ((float*)(sm + OW2))[tid] = __ldg(W2 + tid);

    // ---- A' staging (2 passes in buf0), frags -> registers ----
    u32 bh[4][4][2], bl[4][4][2];
    #pragma unroll 1
    for (int pass = 0; pass < 2; pass++) {
        __syncthreads();
        for (int p = tid; p < 4096; p += 256) {
            int r = p >> 5, dp = p & 31, d = dp * 2;
            int q = qb + 2 * pass + (r >> 6);
            const float* w1r = W1 + (r & 63) * 256;
            float x0 = __ldg(Xb + q * DD + d), x1 = __ldg(Xb + q * DD + d + 1);
            float a0 = fmaf(__ldg(w1r + 192 + d),     x0, __ldg(w1r + 64 + d)     - __ldg(w1r + 128 + d));
            float a1 = fmaf(__ldg(w1r + 192 + d + 1), x1, __ldg(w1r + 64 + d + 1) - __ldg(w1r + 128 + d + 1));
            u32 hp, lp; split2(a0, a1, hp, lp);
            u32 o = SWZ((u32)(r * 128 + dp * 4));
            *(u32*)(sm + OXH(0) + o) = hp;
            *(u32*)(sm + OXL(0) + o) = lp;
        }
        __syncthreads();
        if ((q_w >> 1) == pass) {
            int rbase = (q_w & 1) * 64 + hh * 32;
            #pragma unroll
            for (int nb = 0; nb < 4; nb++)
                #pragma unroll
                for (int ks = 0; ks < 4; ks++) {
                    u32 o = SWZ((u32)((rbase + nb * 8 + (lid & 7)) * 128
                                      + ks * 32 + ((lid >> 3) & 1) * 16));
                    ldsm_x2(bh[nb][ks], smb + OXH(0) + o);
                    ldsm_x2(bl[nb][ks], smb + OXL(0) + o);
                }
        }
    }
    __syncthreads();   // frags loaded; buf0 free

    // ---- prefetch tiles 0 and 1 ----
    {
        const char* sh = g_xh + b * 65536;
        const char* sl = g_xl + b * 65536;
        for (int i = tid; i < 1024; i += 256) {
            cpasync16(smb + OXH(0) + i * 16, sh + i * 16);
            cpasync16(smb + OXL(0) + i * 16, sl + i * 16);
        }
        CP_COMMIT();
        if (nt > 1) {
            for (int i = tid; i < 1024; i += 256) {
                cpasync16(smb + OXH(1) + i * 16, sh + 16384 + i * 16);
                cpasync16(smb + OXL(1) + i * 16, sl + 16384 + i * 16);
            }
        }
        CP_COMMIT();
    }

    const float aslope = __ldg(PA);
    const float b2v    = __ldg(B2);
    float ec[4] = {0.f, 0.f, 0.f, 0.f};

    #pragma unroll 1
    for (int t = 0; t < nt; t++) {
        const int k0 = t << 7;
        const int buf = t & 1;
        const u32 xh_b = smb + OXH(buf), xl_b = smb + OXL(buf);
        CP_WAIT1();
        __syncthreads();

        // ========== S phase: warp = (q_w, 32 h of half hh) ==========
        const int mi_hi = (k0 <= q_mine) ? min(8, ((q_mine - k0) >> 4) + 1) : 0;
        #pragma unroll 1
        for (int mi = 0; mi < mi_hi; mi++) {
            u32 ah[4][4], al[4][4];
            {
                int arow  = mi * 16 + (lid & 15);
                int acolb = (lid >> 4) * 16;
                #pragma unroll
                for (int ks = 0; ks < 4; ks++) {
                    u32 o = SWZ((u32)(arow * 128 + ks * 32 + acolb));
                    ldsm_x4(ah[ks], xh_b + o);
                    ldsm_x4(al[ks], xl_b + o);
                }
            }
            float c[4][4];
            #pragma unroll
            for (int nb = 0; nb < 4; nb++)
                #pragma unroll
                for (int i = 0; i < 4; i++) c[nb][i] = 0.f;
            #pragma unroll
            for (int nb = 0; nb < 4; nb++)
                #pragma unroll
                for (int ks = 0; ks < 4; ks++) {
                    mma_bf16(c[nb], ah[ks], bh[nb][ks]);
                    mma_bf16(c[nb], ah[ks], bl[nb][ks]);
                    mma_bf16(c[nb], al[ks], bh[nb][ks]);
                }
            float s0 = 0.f, s8 = 0.f;
            #pragma unroll
            for (int nb = 0; nb < 4; nb++) {
                int hcol = hh * 32 + nb * 8 + 2 * (lid & 3);
                float2 bias2 = *(const float2*)(sm + OBIAS + (q_w * 64 + hcol) * 4);
                float2 w22   = *(const float2*)(sm + OW2 + hcol * 4);
                float v0 = c[nb][0] + bias2.x, v1 = c[nb][1] + bias2.y;
                float v2 = c[nb][2] + bias2.x, v3 = c[nb][3] + bias2.y;
                float p0 = fmaxf(v0, 0.f) + aslope * fminf(v0, 0.f);
                float p1 = fmaxf(v1, 0.f) + aslope * fminf(v1, 0.f);
                float p2 = fmaxf(v2, 0.f) + aslope * fminf(v2, 0.f);
                float p3 = fmaxf(v3, 0.f) + aslope * fminf(v3, 0.f);
                s0 = fmaf(p0, w22.x, fmaf(p1, w22.y, s0));
                s8 = fmaf(p2, w22.x, fmaf(p3, w22.y, s8));
            }
            s0 += __shfl_xor_sync(0xffffffffu, s0, 1);
            s0 += __shfl_xor_sync(0xffffffffu, s0, 2);
            s8 += __shfl_xor_sync(0xffffffffu, s8, 1);
            s8 += __shfl_xor_sync(0xffffffffu, s8, 2);
            if ((lid & 3) == 0) {
                int kr = mi * 16 + (lid >> 2);
                part[(q_w * 128 + kr) * 2 + hh]     = s0;
                part[(q_w * 128 + kr + 8) * 2 + hh] = s8;
            }
        }
        for (int mi = mi_hi; mi < 8; mi++)
            if (lid < 16) part[(q_w * 128 + mi * 16 + lid) * 2 + hh] = 0.f;
        __syncthreads();

        // ---- combine h-halves -> masked scores, split bf16 hi/lo ----
        for (int p = tid; p < 512; p += 256) {
            int q = p >> 7, kk = p & 127;
            float cm = (k0 + kk <= qb + q) ? __ldg(VM + b * NN + k0 + kk) : 0.f;
            float s = (part[(q * 128 + kk) * 2] + part[(q * 128 + kk) * 2 + 1]
                       + b2v) * cm;
            __nv_bfloat16 h = __float2bfloat16(s);
            __nv_bfloat16 l = __float2bfloat16(s - __bfloat162float(h));
            u32 o = SCSWZ((u32)(q * 256 + kk * 2));
            *(u16*)(sm + OSCH + o) = __bfloat16_as_ushort(h);
            *(u16*)(sm + OSCL + o) = __bfloat16_as_ushort(l);
        }
        __syncthreads();

        // ========== encoded mma: ec += scores . X ==========
        {
            const int srow = lid & 15, scolb = (lid >> 4) * 16;
            #pragma unroll
            for (int kt = 0; kt < 8; kt++) {
                u32 so = SCSWZ((u32)(srow * 256 + kt * 32 + scolb));
                u32 ash[4], asl[4];
                ldsm_x4(ash, smb + OSCH + so);
                ldsm_x4(asl, smb + OSCL + so);
                u32 xo = SWZ((u32)((kt * 16 + (lid & 15)) * 128 + wid * 16));
                u32 bxh[2], bxl[2];
                ldsm_x2t(bxh, xh_b + xo);
                ldsm_x2t(bxl, xl_b + xo);
                mma_bf16(ec, ash, bxh);
                mma_bf16(ec, ash, bxl);
                mma_bf16(ec, asl, bxh);
            }
        }
        __syncthreads();   // buf free for prefetch of t+2

        if (t + 2 < nt) {
            const char* sh = g_xh + b * 65536 + (t + 2) * 16384;
            const char* sl = g_xl + b * 65536 + (t + 2) * 16384;
            for (int i = tid; i < 1024; i += 256) {
                cpasync16(smb + OXH(buf) + i * 16, sh + i * 16);
                cpasync16(smb + OXL(buf) + i * 16, sl + i * 16);
            }
        }
        CP_COMMIT();   // always commit (possibly empty) to keep group count
    }

    // ---- output: rows 0-3 of ec (lanes 0-15, c0/c1) ----
    if (lid < 16) {
        int q = lid >> 2, d0 = wid * 8 + 2 * (lid & 3);
        *(float2*)(OUT + (b * NN + qb + q) * DD + d0) = make_float2(ec[0], ec[1]);
    }
}

// ---------------------------------------------------------------------------
// Inputs (metadata order):
//  0 past_lengths (unused)  1 user_embeddings [8,512,64] f32  2 valid_mask [8,512]
//  3 W1 [64,256]  4 b1 [64]  5 prelu_a [1]  6 W2 [1,64]  7 b2 [1]
// Output: encoded [8,512,64] f32
// ---------------------------------------------------------------------------
extern "C" void kernel_launch(void* const* d_in, const int* in_sizes, int n_in,
                              void* d_out, int out_size)
{
    const float* X  = (const float*)d_in[1];
    const float* VM = (const float*)d_in[2];
    const float* W1 = (const float*)d_in[3];
    const float* b1 = (const float*)d_in[4];
    const float* pa = (const float*)d_in[5];
    const float* W2 = (const float*)d_in[6];
    const float* b2 = (const float*)d_in[7];
    float* OUT = (float*)d_out;

    cudaFuncSetAttribute(din_mma, cudaFuncAttributeMaxDynamicSharedMemorySize, SMEM_DYN);
    xsplit<<<32, 256>>>(X);
    precompute_hq<<<256, 64>>>(X, W1, b1);
    din_mma<<<BB * NN / 4, 256, SMEM_DYN>>>(X, VM, W1, pa, W2, b2, OUT);
}

// round 8
// speedup vs baseline: 2.5722x; 1.2096x over previous
#include <cuda_runtime.h>
#include <cuda_bf16.h>

#define BB 8
#define NN 512
#define DD 64

typedef unsigned int u32;
typedef unsigned short u16;

#define SWZ(o)   ((o) ^ (((o) >> 3) & 0x70))   // 128B-row swizzle
#define SCSWZ(o) ((o) ^ (((o) >> 4) & 0x70))   // 256B-row swizzle (scores)

// global scratch: X split into bf16 hi/lo, swizzled tile-ready layout
__device__ char  g_xh[BB * 4 * 16384];   // [b][tile][SWZ(row*128+dp*4)]
__device__ char  g_xl[BB * 4 * 16384];
__device__ float g_hq[BB * NN * 64];     // hq + b1

// ---- dynamic smem offsets (per-CTA) ----
#define OXH(buf) ((buf) * 32768)
#define OXL(buf) ((buf) * 32768 + 16384)
#define OSCH  65536                      // scores hi [8][256B]
#define OSCL  67584                      // scores lo [8][256B]
#define OPART 69632                      // 2q*128k*2 halves f32 = 2KB
#define OBIAS 71680                      // 2*64 f32
#define OW2   72192                      // 64 f32
#define SMEM_DYN 72448

static __device__ __forceinline__ u32 smem_u32(const void* p) {
    u32 a;
    asm("{ .reg .u64 t; cvta.to.shared.u64 t, %1; cvt.u32.u64 %0, t; }" : "=r"(a) : "l"(p));
    return a;
}
static __device__ __forceinline__ void ldsm_x4(u32* r, u32 addr) {
    asm volatile("ldmatrix.sync.aligned.m8n8.x4.shared.b16 {%0,%1,%2,%3}, [%4];"
        : "=r"(r[0]), "=r"(r[1]), "=r"(r[2]), "=r"(r[3]) : "r"(addr));
}
static __device__ __forceinline__ void ldsm_x2(u32* r, u32 addr) {
    asm volatile("ldmatrix.sync.aligned.m8n8.x2.shared.b16 {%0,%1}, [%2];"
        : "=r"(r[0]), "=r"(r[1]) : "r"(addr));
}
static __device__ __forceinline__ void ldsm_x2t(u32* r, u32 addr) {
    asm volatile("ldmatrix.sync.aligned.m8n8.x2.trans.shared.b16 {%0,%1}, [%2];"
        : "=r"(r[0]), "=r"(r[1]) : "r"(addr));
}
static __device__ __forceinline__ void mma_bf16(float* c, const u32* a, const u32* b) {
    asm volatile("mma.sync.aligned.m16n8k16.row.col.f32.bf16.bf16.f32 "
        "{%0,%1,%2,%3}, {%4,%5,%6,%7}, {%8,%9}, {%0,%1,%2,%3};"
        : "+f"(c[0]), "+f"(c[1]), "+f"(c[2]), "+f"(c[3])
        : "r"(a[0]), "r"(a[1]), "r"(a[2]), "r"(a[3]), "r"(b[0]), "r"(b[1]));
}
static __device__ __forceinline__ void split2(float a0, float a1, u32& hp, u32& lp) {
    __nv_bfloat16 h0 = __float2bfloat16(a0), h1 = __float2bfloat16(a1);
    __nv_bfloat16 l0 = __float2bfloat16(a0 - __bfloat162float(h0));
    __nv_bfloat16 l1 = __float2bfloat16(a1 - __bfloat162float(h1));
    hp = (u32)__bfloat16_as_ushort(h0) | ((u32)__bfloat16_as_ushort(h1) << 16);
    lp = (u32)__bfloat16_as_ushort(l0) | ((u32)__bfloat16_as_ushort(l1) << 16);
}
static __device__ __forceinline__ void cpasync16(u32 saddr, const void* gptr) {
    asm volatile("{ .reg .u64 g; cvta.to.global.u64 g, %1; "
                 "cp.async.ca.shared.global [%0], [g], 16; }"
                 :: "r"(saddr), "l"(gptr));
}
#define CP_COMMIT() asm volatile("cp.async.commit_group;" ::: "memory")
#define CP_WAIT1()  asm volatile("cp.async.wait_group 1;" ::: "memory")

// ---------------------------------------------------------------------------
// Fused prep: (a) split X rows into bf16 hi/lo swizzled tiles,
//             (b) hq[b,n,h] = x . (Wq+Wd)[h,:] + b1[h].
// Grid 256 = 8b x 32 slices of 16 rows; 128 threads.
// ---------------------------------------------------------------------------
__global__ __launch_bounds__(128) void prep(
    const float* __restrict__ X, const float* __restrict__ W1,
    const float* __restrict__ B1)
{
    __shared__ float sx[16 * DD];
    const int tid = threadIdx.x, b = blockIdx.x >> 5, n0 = (blockIdx.x & 31) * 16;
    for (int i = tid; i < 256; i += 128)
        reinterpret_cast<float4*>(sx)[i] =
            reinterpret_cast<const float4*>(X + (b * NN + n0) * DD)[i];
    __syncthreads();

    // ---- xsplit part: 512 items ----
    {
        const int t = n0 >> 7, rbase = n0 & 127;
        char* dh = g_xh + b * 65536 + t * 16384;
        char* dl = g_xl + b * 65536 + t * 16384;
        #pragma unroll 4
        for (int p = tid; p < 512; p += 128) {
            int r = p >> 5, dp = p & 31;
            float2 v = *(const float2*)(sx + r * DD + dp * 2);
            u32 hp, lp; split2(v.x, v.y, hp, lp);
            u32 o = SWZ((u32)((rbase + r) * 128 + dp * 4));
            *(u32*)(dh + o) = hp;
            *(u32*)(dl + o) = lp;
        }
    }
    // ---- hq part: threads 0..63, thread = h ----
    if (tid < 64) {
        const float bb = __ldg(B1 + tid);
        const float4* w1row = reinterpret_cast<const float4*>(W1 + tid * 256);
        float4 w[16];
        #pragma unroll
        for (int j = 0; j < 16; j++) {
            float4 wq = __ldg(&w1row[j]);
            float4 wd = __ldg(&w1row[32 + j]);
            w[j] = make_float4(wq.x + wd.x, wq.y + wd.y, wq.z + wd.z, wq.w + wd.w);
        }
        for (int nn = 0; nn < 16; nn++) {
            const float4* xr = reinterpret_cast<const float4*>(sx + nn * DD);
            float s = 0.f;
            #pragma unroll
            for (int j = 0; j < 16; j++) {
                float4 xv = xr[j];
                s += w[j].x * xv.x + w[j].y * xv.y + w[j].z * xv.z + w[j].w * xv.w;
            }
            g_hq[(b * NN + n0 + nn) * 64 + tid] = s + bb;
        }
    }
}

// ---------------------------------------------------------------------------
// Main. One CTA = (b, queries qb, qb+1). 4 warps = 2 q x 2 h-halves.
// ~3 CTAs/SM so independent CTAs overlap each other's phases.
// A'(q,32h) mma B-frags in registers; X tiles cp.async double-buffered.
// ---------------------------------------------------------------------------
__global__ __launch_bounds__(128) void din_mma(
    const float* __restrict__ X, const float* __restrict__ VM,
    const float* __restrict__ W1, const float* __restrict__ PA,
    const float* __restrict__ W2, const float* __restrict__ B2,
    float* __restrict__ OUT)
{
    extern __shared__ __align__(128) char sm[];
    const u32 smb = smem_u32(sm);

    const int tid = threadIdx.x, wid = tid >> 5, lid = tid & 31;
    const int q_w = wid >> 1, hh = wid & 1;
    const int b = blockIdx.x & 7, g = blockIdx.x >> 3;      // g 0..255
    const int qb = 2 * (255 - g);              // long queries first
    const int q_mine = qb + q_w;
    const int nt = ((qb + 1) >> 7) + 1;
    const float* Xb = X + b * NN * DD;
    float* part = (float*)(sm + OPART);

    // zero score buffers (rows 2-7 stay zero forever)
    for (int p = tid; p < 1024; p += 128) ((u32*)(sm + OSCH))[p] = 0;
    // bias from precomputed hq
    ((float*)(sm + OBIAS))[tid] = g_hq[(b * NN + qb + (tid >> 6)) * 64 + (tid & 63)];
    if (tid < 64) ((float*)(sm + OW2))[tid] = __ldg(W2 + tid);

    // ---- A' staging (one pass, 128 rows = 2q x 64h), frags -> registers ----
    u32 bh[4][4][2], bl[4][4][2];
    for (int p = tid; p < 4096; p += 128) {
        int r = p >> 5, dp = p & 31, d = dp * 2;
        int q = qb + (r >> 6);
        const float* w1r = W1 + (r & 63) * 256;
        float x0 = __ldg(Xb + q * DD + d), x1 = __ldg(Xb + q * DD + d + 1);
        float a0 = fmaf(__ldg(w1r + 192 + d),     x0, __ldg(w1r + 64 + d)     - __ldg(w1r + 128 + d));
        float a1 = fmaf(__ldg(w1r + 192 + d + 1), x1, __ldg(w1r + 64 + d + 1) - __ldg(w1r + 128 + d + 1));
        u32 hp, lp; split2(a0, a1, hp, lp);
        u32 o = SWZ((u32)(r * 128 + dp * 4));
        *(u32*)(sm + OXH(0) + o) = hp;
        *(u32*)(sm + OXL(0) + o) = lp;
    }
    __syncthreads();
    {
        int rbase = q_w * 64 + hh * 32;
        #pragma unroll
        for (int nb = 0; nb < 4; nb++)
            #pragma unroll
            for (int ks = 0; ks < 4; ks++) {
                u32 o = SWZ((u32)((rbase + nb * 8 + (lid & 7)) * 128
                                  + ks * 32 + ((lid >> 3) & 1) * 16));
                ldsm_x2(bh[nb][ks], smb + OXH(0) + o);
                ldsm_x2(bl[nb][ks], smb + OXL(0) + o);
            }
    }
    __syncthreads();   // frags loaded; buf0 free

    // ---- prefetch tiles 0 and 1 ----
    {
        const char* sh = g_xh + b * 65536;
        const char* sl = g_xl + b * 65536;
        for (int i = tid; i < 1024; i += 128) {
            cpasync16(smb + OXH(0) + i * 16, sh + i * 16);
            cpasync16(smb + OXL(0) + i * 16, sl + i * 16);
        }
        CP_COMMIT();
        if (nt > 1) {
            for (int i = tid; i < 1024; i += 128) {
                cpasync16(smb + OXH(1) + i * 16, sh + 16384 + i * 16);
                cpasync16(smb + OXL(1) + i * 16, sl + 16384 + i * 16);
            }
        }
        CP_COMMIT();
    }

    const float aslope = __ldg(PA);
    const float b2v    = __ldg(B2);
    const u32 zreg = 0;
    float ec0[4] = {0.f, 0.f, 0.f, 0.f};
    float ec1[4] = {0.f, 0.f, 0.f, 0.f};

    #pragma unroll 1
    for (int t = 0; t < nt; t++) {
        const int k0 = t << 7;
        const int buf = t & 1;
        const u32 xh_b = smb + OXH(buf), xl_b = smb + OXL(buf);
        CP_WAIT1();
        __syncthreads();

        // ========== S phase: warp = (q_w, 32 h of half hh) ==========
        const int mi_hi = (k0 <= q_mine) ? min(8, ((q_mine - k0) >> 4) + 1) : 0;
        #pragma unroll 1
        for (int mi = 0; mi < mi_hi; mi++) {
            u32 ah[4][4], al[4][4];
            {
                int arow  = mi * 16 + (lid & 15);
                int acolb = (lid >> 4) * 16;
                #pragma unroll
                for (int ks = 0; ks < 4; ks++) {
                    u32 o = SWZ((u32)(arow * 128 + ks * 32 + acolb));
                    ldsm_x4(ah[ks], xh_b + o);
                    ldsm_x4(al[ks], xl_b + o);
                }
            }
            float c[4][4];
            #pragma unroll
            for (int nb = 0; nb < 4; nb++)
                #pragma unroll
                for (int i = 0; i < 4; i++) c[nb][i] = 0.f;
            #pragma unroll
            for (int nb = 0; nb < 4; nb++)
                #pragma unroll
                for (int ks = 0; ks < 4; ks++) {
                    mma_bf16(c[nb], ah[ks], bh[nb][ks]);
                    mma_bf16(c[nb], ah[ks], bl[nb][ks]);
                    mma_bf16(c[nb], al[ks], bh[nb][ks]);
                }
            float s0 = 0.f, s8 = 0.f;
            #pragma unroll
            for (int nb = 0; nb < 4; nb++) {
                int hcol = hh * 32 + nb * 8 + 2 * (lid & 3);
                float2 bias2 = *(const float2*)(sm + OBIAS + (q_w * 64 + hcol) * 4);
                float2 w22   = *(const float2*)(sm + OW2 + hcol * 4);
                float v0 = c[nb][0] + bias2.x, v1 = c[nb][1] + bias2.y;
                float v2 = c[nb][2] + bias2.x, v3 = c[nb][3] + bias2.y;
                float p0 = fmaxf(v0, 0.f) + aslope * fminf(v0, 0.f);
                float p1 = fmaxf(v1, 0.f) + aslope * fminf(v1, 0.f);
                float p2 = fmaxf(v2, 0.f) + aslope * fminf(v2, 0.f);
                float p3 = fmaxf(v3, 0.f) + aslope * fminf(v3, 0.f);
                s0 = fmaf(p0, w22.x, fmaf(p1, w22.y, s0));
                s8 = fmaf(p2, w22.x, fmaf(p3, w22.y, s8));
            }
            s0 += __shfl_xor_sync(0xffffffffu, s0, 1);
            s0 += __shfl_xor_sync(0xffffffffu, s0, 2);
            s8 += __shfl_xor_sync(0xffffffffu, s8, 1);
            s8 += __shfl_xor_sync(0xffffffffu, s8, 2);
            if ((lid & 3) == 0) {
                int kr = mi * 16 + (lid >> 2);
                part[(q_w * 128 + kr) * 2 + hh]     = s0;
                part[(q_w * 128 + kr + 8) * 2 + hh] = s8;
            }
        }
        for (int mi = mi_hi; mi < 8; mi++)
            if (lid < 16) part[(q_w * 128 + mi * 16 + lid) * 2 + hh] = 0.f;
        __syncthreads();

        // ---- combine h-halves -> masked scores, split bf16 hi/lo ----
        for (int p = tid; p < 256; p += 128) {
            int q = p >> 7, kk = p & 127;
            float cm = (k0 + kk <= qb + q) ? __ldg(VM + b * NN + k0 + kk) : 0.f;
            float s = (part[(q * 128 + kk) * 2] + part[(q * 128 + kk) * 2 + 1]
                       + b2v) * cm;
            __nv_bfloat16 h = __float2bfloat16(s);
            __nv_bfloat16 l = __float2bfloat16(s - __bfloat162float(h));
            u32 o = SCSWZ((u32)(q * 256 + kk * 2));
            *(u16*)(sm + OSCH + o) = __bfloat16_as_ushort(h);
            *(u16*)(sm + OSCL + o) = __bfloat16_as_ushort(l);
        }
        __syncthreads();

        // ========== encoded mma: ec += scores . X (warp: 16 d cols) ==========
        {
            const int srow = lid & 7, sblk = (lid >> 3) & 1;
            #pragma unroll
            for (int kt = 0; kt < 8; kt++) {
                u32 so = SCSWZ((u32)(srow * 256 + kt * 32 + sblk * 16));
                u32 sh2[2], sl2[2];
                ldsm_x2(sh2, smb + OSCH + so);     // rows 0-7 only (8-15 zero)
                ldsm_x2(sl2, smb + OSCL + so);
                u32 ash[4] = { sh2[0], zreg, sh2[1], zreg };
                u32 asl[4] = { sl2[0], zreg, sl2[1], zreg };
                u32 xo = SWZ((u32)((kt * 16 + (lid & 15)) * 128 + wid * 32));
                u32 bxh0[2], bxl0[2], bxh1[2], bxl1[2];
                ldsm_x2t(bxh0, xh_b + xo);
                ldsm_x2t(bxl0, xl_b + xo);
                u32 xo1 = SWZ((u32)((kt * 16 + (lid & 15)) * 128 + wid * 32 + 16));
                ldsm_x2t(bxh1, xh_b + xo1);
                ldsm_x2t(bxl1, xl_b + xo1);
                mma_bf16(ec0, ash, bxh0);
                mma_bf16(ec0, ash, bxl0);
                mma_bf16(ec0, asl, bxh0);
                mma_bf16(ec1, ash, bxh1);
                mma_bf16(ec1, ash, bxl1);
                mma_bf16(ec1, asl, bxh1);
            }
        }
        __syncthreads();   // buf free for prefetch of t+2

        if (t + 2 < nt) {
            const char* sh = g_xh + b * 65536 + (t + 2) * 16384;
            const char* sl = g_xl + b * 65536 + (t + 2) * 16384;
            for (int i = tid; i < 1024; i += 128) {
                cpasync16(smb + OXH(buf) + i * 16, sh + i * 16);
                cpasync16(smb + OXL(buf) + i * 16, sl + i * 16);
            }
        }
        CP_COMMIT();   // always commit (possibly empty) to keep group count
    }

    // ---- output: rows 0-1 of ec0/ec1 (lanes 0-7) ----
    if (lid < 8) {
        int q = lid >> 2, d0 = wid * 16 + 2 * (lid & 3);
        *(float2*)(OUT + (b * NN + qb + q) * DD + d0)     = make_float2(ec0[0], ec0[1]);
        *(float2*)(OUT + (b * NN + qb + q) * DD + d0 + 8) = make_float2(ec1[0], ec1[1]);
    }
}

// ---------------------------------------------------------------------------
// Inputs (metadata order):
//  0 past_lengths (unused)  1 user_embeddings [8,512,64] f32  2 valid_mask [8,512]
//  3 W1 [64,256]  4 b1 [64]  5 prelu_a [1]  6 W2 [1,64]  7 b2 [1]
// Output: encoded [8,512,64] f32
// ---------------------------------------------------------------------------
extern "C" void kernel_launch(void* const* d_in, const int* in_sizes, int n_in,
                              void* d_out, int out_size)
{
    const float* X  = (const float*)d_in[1];
    const float* VM = (const float*)d_in[2];
    const float* W1 = (const float*)d_in[3];
    const float* b1 = (const float*)d_in[4];
    const float* pa = (const float*)d_in[5];
    const float* W2 = (const float*)d_in[6];
    const float* b2 = (const float*)d_in[7];
    float* OUT = (float*)d_out;

    cudaFuncSetAttribute(din_mma, cudaFuncAttributeMaxDynamicSharedMemorySize, SMEM_DYN);
    prep<<<256, 128>>>(X, W1, b1);
    din_mma<<<BB * NN / 2, 128, SMEM_DYN>>>(X, VM, W1, pa, W2, b2, OUT);
}

// round 9
// speedup vs baseline: 2.6988x; 1.0492x over previous
#include <cuda_runtime.h>
#include <cuda_bf16.h>

#define BB 8
#define NN 512
#define DD 64

typedef unsigned int u32;
typedef unsigned short u16;

#define SWZ(o)   ((o) ^ (((o) >> 3) & 0x70))   // 128B-row swizzle
#define SCSWZ(o) ((o) ^ (((o) >> 4) & 0x70))   // 256B-row swizzle (scores)

// global scratch: X split into bf16 hi/lo, swizzled tile-ready layout
__device__ char  g_xh[BB * 4 * 16384];   // [b][tile][SWZ(row*128+dp*4)]
__device__ char  g_xl[BB * 4 * 16384];
__device__ float g_hq[BB * NN * 64];     // hq + b1

// ---- dynamic smem offsets (per-CTA), single X buffer ----
#define OXH   0
#define OXL   16384
#define OSCH  32768                      // scores hi [8][256B]
#define OSCL  34816                      // scores lo [8][256B]
#define OPART 36864                      // 2q*128k*2 halves f32 = 2KB
#define OBIAS 38912                      // 2*64 f32
#define OW2   39424                      // 64 f32
#define SMEM_DYN 39680

static __device__ __forceinline__ u32 smem_u32(const void* p) {
    u32 a;
    asm("{ .reg .u64 t; cvta.to.shared.u64 t, %1; cvt.u32.u64 %0, t; }" : "=r"(a) : "l"(p));
    return a;
}
static __device__ __forceinline__ void ldsm_x4(u32* r, u32 addr) {
    asm volatile("ldmatrix.sync.aligned.m8n8.x4.shared.b16 {%0,%1,%2,%3}, [%4];"
        : "=r"(r[0]), "=r"(r[1]), "=r"(r[2]), "=r"(r[3]) : "r"(addr));
}
static __device__ __forceinline__ void ldsm_x2(u32* r, u32 addr) {
    asm volatile("ldmatrix.sync.aligned.m8n8.x2.shared.b16 {%0,%1}, [%2];"
        : "=r"(r[0]), "=r"(r[1]) : "r"(addr));
}
static __device__ __forceinline__ void ldsm_x2t(u32* r, u32 addr) {
    asm volatile("ldmatrix.sync.aligned.m8n8.x2.trans.shared.b16 {%0,%1}, [%2];"
        : "=r"(r[0]), "=r"(r[1]) : "r"(addr));
}
static __device__ __forceinline__ void mma_bf16(float* c, const u32* a, const u32* b) {
    asm volatile("mma.sync.aligned.m16n8k16.row.col.f32.bf16.bf16.f32 "
        "{%0,%1,%2,%3}, {%4,%5,%6,%7}, {%8,%9}, {%0,%1,%2,%3};"
        : "+f"(c[0]), "+f"(c[1]), "+f"(c[2]), "+f"(c[3])
        : "r"(a[0]), "r"(a[1]), "r"(a[2]), "r"(a[3]), "r"(b[0]), "r"(b[1]));
}
static __device__ __forceinline__ void split2(float a0, float a1, u32& hp, u32& lp) {
    __nv_bfloat16 h0 = __float2bfloat16(a0), h1 = __float2bfloat16(a1);
    __nv_bfloat16 l0 = __float2bfloat16(a0 - __bfloat162float(h0));
    __nv_bfloat16 l1 = __float2bfloat16(a1 - __bfloat162float(h1));
    hp = (u32)__bfloat16_as_ushort(h0) | ((u32)__bfloat16_as_ushort(h1) << 16);
    lp = (u32)__bfloat16_as_ushort(l0) | ((u32)__bfloat16_as_ushort(l1) << 16);
}
static __device__ __forceinline__ void cpasync16(u32 saddr, const void* gptr) {
    asm volatile("{ .reg .u64 g; cvta.to.global.u64 g, %1; "
                 "cp.async.ca.shared.global [%0], [g], 16; }"
                 :: "r"(saddr), "l"(gptr));
}
#define CP_COMMIT() asm volatile("cp.async.commit_group;" ::: "memory")
#define CP_WAIT0()  asm volatile("cp.async.wait_group 0;" ::: "memory")

// ---------------------------------------------------------------------------
// Fused prep: (a) split X rows into bf16 hi/lo swizzled tiles,
//             (b) hq[b,n,h] = x . (Wq+Wd)[h,:] + b1[h].
// ---------------------------------------------------------------------------
__global__ __launch_bounds__(128) void prep(
    const float* __restrict__ X, const float* __restrict__ W1,
    const float* __restrict__ B1)
{
    __shared__ float sx[16 * DD];
    const int tid = threadIdx.x, b = blockIdx.x >> 5, n0 = (blockIdx.x & 31) * 16;
    for (int i = tid; i < 256; i += 128)
        reinterpret_cast<float4*>(sx)[i] =
            reinterpret_cast<const float4*>(X + (b * NN + n0) * DD)[i];
    __syncthreads();

    {   // xsplit part
        const int t = n0 >> 7, rbase = n0 & 127;
        char* dh = g_xh + b * 65536 + t * 16384;
        char* dl = g_xl + b * 65536 + t * 16384;
        #pragma unroll 4
        for (int p = tid; p < 512; p += 128) {
            int r = p >> 5, dp = p & 31;
            float2 v = *(const float2*)(sx + r * DD + dp * 2);
            u32 hp, lp; split2(v.x, v.y, hp, lp);
            u32 o = SWZ((u32)((rbase + r) * 128 + dp * 4));
            *(u32*)(dh + o) = hp;
            *(u32*)(dl + o) = lp;
        }
    }
    if (tid < 64) {   // hq part, thread = h
        const float bb = __ldg(B1 + tid);
        const float4* w1row = reinterpret_cast<const float4*>(W1 + tid * 256);
        float4 w[16];
        #pragma unroll
        for (int j = 0; j < 16; j++) {
            float4 wq = __ldg(&w1row[j]);
            float4 wd = __ldg(&w1row[32 + j]);
            w[j] = make_float4(wq.x + wd.x, wq.y + wd.y, wq.z + wd.z, wq.w + wd.w);
        }
        for (int nn = 0; nn < 16; nn++) {
            const float4* xr = reinterpret_cast<const float4*>(sx + nn * DD);
            float s = 0.f;
            #pragma unroll
            for (int j = 0; j < 16; j++) {
                float4 xv = xr[j];
                s += w[j].x * xv.x + w[j].y * xv.y + w[j].z * xv.z + w[j].w * xv.w;
            }
            g_hq[(b * NN + n0 + nn) * 64 + tid] = s + bb;
        }
    }
}

// ---------------------------------------------------------------------------
// Main. One CTA = (b, queries qb, qb+1). 4 warps = 2 q x 2 h-halves.
// Single X buffer -> ~40KB smem -> 5 CTAs/SM; cross-CTA overlap hides the
// per-tile staging latency. A'(q,32h) mma B-frags live in registers.
// ---------------------------------------------------------------------------
__global__ __launch_bounds__(128) void din_mma(
    const float* __restrict__ X, const float* __restrict__ VM,
    const float* __restrict__ W1, const float* __restrict__ PA,
    const float* __restrict__ W2, const float* __restrict__ B2,
    float* __restrict__ OUT)
{
    extern __shared__ __align__(128) char sm[];
    const u32 smb = smem_u32(sm);

    const int tid = threadIdx.x, wid = tid >> 5, lid = tid & 31;
    const int q_w = wid >> 1, hh = wid & 1;
    const int b = blockIdx.x & 7, g = blockIdx.x >> 3;      // g 0..255
    const int qb = 2 * (255 - g);              // long queries first
    const int q_mine = qb + q_w;
    const int nt = ((qb + 1) >> 7) + 1;
    const float* Xb = X + b * NN * DD;
    float* part = (float*)(sm + OPART);

    // zero score buffers (rows 2-7 stay zero forever)
    for (int p = tid; p < 1024; p += 128) ((u32*)(sm + OSCH))[p] = 0;
    // bias from precomputed hq
    ((float*)(sm + OBIAS))[tid] = g_hq[(b * NN + qb + (tid >> 6)) * 64 + (tid & 63)];
    if (tid < 64) ((float*)(sm + OW2))[tid] = __ldg(W2 + tid);

    // ---- A' staging (128 rows = 2q x 64h) into X buffer, frags -> regs ----
    u32 bh[4][4][2], bl[4][4][2];
    for (int p = tid; p < 4096; p += 128) {
        int r = p >> 5, dp = p & 31, d = dp * 2;
        int q = qb + (r >> 6);
        const float* w1r = W1 + (r & 63) * 256;
        float x0 = __ldg(Xb + q * DD + d), x1 = __ldg(Xb + q * DD + d + 1);
        float a0 = fmaf(__ldg(w1r + 192 + d),     x0, __ldg(w1r + 64 + d)     - __ldg(w1r + 128 + d));
        float a1 = fmaf(__ldg(w1r + 192 + d + 1), x1, __ldg(w1r + 64 + d + 1) - __ldg(w1r + 128 + d + 1));
        u32 hp, lp; split2(a0, a1, hp, lp);
        u32 o = SWZ((u32)(r * 128 + dp * 4));
        *(u32*)(sm + OXH + o) = hp;
        *(u32*)(sm + OXL + o) = lp;
    }
    __syncthreads();
    {
        int rbase = q_w * 64 + hh * 32;
        #pragma unroll
        for (int nb = 0; nb < 4; nb++)
            #pragma unroll
            for (int ks = 0; ks < 4; ks++) {
                u32 o = SWZ((u32)((rbase + nb * 8 + (lid & 7)) * 128
                                  + ks * 32 + ((lid >> 3) & 1) * 16));
                ldsm_x2(bh[nb][ks], smb + OXH + o);
                ldsm_x2(bl[nb][ks], smb + OXL + o);
            }
    }
    // hoist warp-constant bias/W2 pairs into registers
    float2 bias2r[4], w22r[4];
    #pragma unroll
    for (int nb = 0; nb < 4; nb++) {
        int hcol = hh * 32 + nb * 8 + 2 * (lid & 3);
        bias2r[nb] = *(const float2*)(sm + OBIAS + (q_w * 64 + hcol) * 4);
        w22r[nb]   = *(const float2*)(sm + OW2 + hcol * 4);
    }
    __syncthreads();   // frags + constants loaded; buffer free

    // ---- prefetch tile 0 ----
    {
        const char* sh = g_xh + b * 65536;
        const char* sl = g_xl + b * 65536;
        for (int i = tid; i < 1024; i += 128) {
            cpasync16(smb + OXH + i * 16, sh + i * 16);
            cpasync16(smb + OXL + i * 16, sl + i * 16);
        }
        CP_COMMIT();
    }

    const float aslope = __ldg(PA);
    const float b2v    = __ldg(B2);
    const u32 zreg = 0;
    float ec0[4] = {0.f, 0.f, 0.f, 0.f};
    float ec1[4] = {0.f, 0.f, 0.f, 0.f};

    #pragma unroll 1
    for (int t = 0; t < nt; t++) {
        const int k0 = t << 7;
        const u32 xh_b = smb + OXH, xl_b = smb + OXL;
        CP_WAIT0();
        __syncthreads();

        // ========== S phase: warp = (q_w, 32 h of half hh) ==========
        const int mi_hi = (k0 <= q_mine) ? min(8, ((q_mine - k0) >> 4) + 1) : 0;
        #pragma unroll 1
        for (int mi = 0; mi < mi_hi; mi++) {
            u32 ah[4][4], al[4][4];
            {
                int arow  = mi * 16 + (lid & 15);
                int acolb = (lid >> 4) * 16;
                #pragma unroll
                for (int ks = 0; ks < 4; ks++) {
                    u32 o = SWZ((u32)(arow * 128 + ks * 32 + acolb));
                    ldsm_x4(ah[ks], xh_b + o);
                    ldsm_x4(al[ks], xl_b + o);
                }
            }
            float c[4][4];
            #pragma unroll
            for (int nb = 0; nb < 4; nb++)
                #pragma unroll
                for (int i = 0; i < 4; i++) c[nb][i] = 0.f;
            #pragma unroll
            for (int nb = 0; nb < 4; nb++)
                #pragma unroll
                for (int ks = 0; ks < 4; ks++) {
                    mma_bf16(c[nb], ah[ks], bh[nb][ks]);
                    mma_bf16(c[nb], ah[ks], bl[nb][ks]);
                    mma_bf16(c[nb], al[ks], bh[nb][ks]);
                }
            float s0 = 0.f, s8 = 0.f;
            #pragma unroll
            for (int nb = 0; nb < 4; nb++) {
                float v0 = c[nb][0] + bias2r[nb].x, v1 = c[nb][1] + bias2r[nb].y;
                float v2 = c[nb][2] + bias2r[nb].x, v3 = c[nb][3] + bias2r[nb].y;
                float p0 = fmaxf(v0, 0.f) + aslope * fminf(v0, 0.f);
                float p1 = fmaxf(v1, 0.f) + aslope * fminf(v1, 0.f);
                float p2 = fmaxf(v2, 0.f) + aslope * fminf(v2, 0.f);
                float p3 = fmaxf(v3, 0.f) + aslope * fminf(v3, 0.f);
                s0 = fmaf(p0, w22r[nb].x, fmaf(p1, w22r[nb].y, s0));
                s8 = fmaf(p2, w22r[nb].x, fmaf(p3, w22r[nb].y, s8));
            }
            s0 += __shfl_xor_sync(0xffffffffu, s0, 1);
            s0 += __shfl_xor_sync(0xffffffffu, s0, 2);
            s8 += __shfl_xor_sync(0xffffffffu, s8, 1);
            s8 += __shfl_xor_sync(0xffffffffu, s8, 2);
            if ((lid & 3) == 0) {
                int kr = mi * 16 + (lid >> 2);
                part[(q_w * 128 + kr) * 2 + hh]     = s0;
                part[(q_w * 128 + kr + 8) * 2 + hh] = s8;
            }
        }
        for (int mi = mi_hi; mi < 8; mi++)
            if (lid < 16) part[(q_w * 128 + mi * 16 + lid) * 2 + hh] = 0.f;
        __syncthreads();

        // ---- combine h-halves -> masked scores, split bf16 hi/lo ----
        for (int p = tid; p < 256; p += 128) {
            int q = p >> 7, kk = p & 127;
            float cm = (k0 + kk <= qb + q) ? __ldg(VM + b * NN + k0 + kk) : 0.f;
            float s = (part[(q * 128 + kk) * 2] + part[(q * 128 + kk) * 2 + 1]
                       + b2v) * cm;
            __nv_bfloat16 h = __float2bfloat16(s);
            __nv_bfloat16 l = __float2bfloat16(s - __bfloat162float(h));
            u32 o = SCSWZ((u32)(q * 256 + kk * 2));
            *(u16*)(sm + OSCH + o) = __bfloat16_as_ushort(h);
            *(u16*)(sm + OSCL + o) = __bfloat16_as_ushort(l);
        }
        __syncthreads();

        // ========== encoded mma: ec += scores . X (causally bounded) ========
        {
            const int kt_hi = min(8, ((qb + 1 - k0) >> 4) + 1);
            const int srow = lid & 7, sblk = (lid >> 3) & 1;
            #pragma unroll 1
            for (int kt = 0; kt < kt_hi; kt++) {
                u32 so = SCSWZ((u32)(srow * 256 + kt * 32 + sblk * 16));
                u32 sh2[2], sl2[2];
                ldsm_x2(sh2, smb + OSCH + so);     // rows 0-7 only (2-7 zero)
                ldsm_x2(sl2, smb + OSCL + so);
                u32 ash[4] = { sh2[0], zreg, sh2[1], zreg };
                u32 asl[4] = { sl2[0], zreg, sl2[1], zreg };
                u32 xo = SWZ((u32)((kt * 16 + (lid & 15)) * 128 + wid * 32));
                u32 bxh0[2], bxl0[2], bxh1[2], bxl1[2];
                ldsm_x2t(bxh0, xh_b + xo);
                ldsm_x2t(bxl0, xl_b + xo);
                u32 xo1 = SWZ((u32)((kt * 16 + (lid & 15)) * 128 + wid * 32 + 16));
                ldsm_x2t(bxh1, xh_b + xo1);
                ldsm_x2t(bxl1, xl_b + xo1);
                mma_bf16(ec0, ash, bxh0);
                mma_bf16(ec0, ash, bxl0);
                mma_bf16(ec0, asl, bxh0);
                mma_bf16(ec1, ash, bxh1);
                mma_bf16(ec1, ash, bxl1);
                mma_bf16(ec1, asl, bxh1);
            }
        }
        __syncthreads();   // buffer free for next tile's prefetch

        if (t + 1 < nt) {
            const char* sh = g_xh + b * 65536 + (t + 1) * 16384;
            const char* sl = g_xl + b * 65536 + (t + 1) * 16384;
            for (int i = tid; i < 1024; i += 128) {
                cpasync16(smb + OXH + i * 16, sh + i * 16);
                cpasync16(smb + OXL + i * 16, sl + i * 16);
            }
            CP_COMMIT();
        }
    }

    // ---- output: rows 0-1 of ec0/ec1 (lanes 0-7) ----
    if (lid < 8) {
        int q = lid >> 2, d0 = wid * 16 + 2 * (lid & 3);
        *(float2*)(OUT + (b * NN + qb + q) * DD + d0)     = make_float2(ec0[0], ec0[1]);
        *(float2*)(OUT + (b * NN + qb + q) * DD + d0 + 8) = make_float2(ec1[0], ec1[1]);
    }
}

// ---------------------------------------------------------------------------
// Inputs (metadata order):
//  0 past_lengths (unused)  1 user_embeddings [8,512,64] f32  2 valid_mask [8,512]
//  3 W1 [64,256]  4 b1 [64]  5 prelu_a [1]  6 W2 [1,64]  7 b2 [1]
// Output: encoded [8,512,64] f32
// ---------------------------------------------------------------------------
extern "C" void kernel_launch(void* const* d_in, const int* in_sizes, int n_in,
                              void* d_out, int out_size)
{
    const float* X  = (const float*)d_in[1];
    const float* VM = (const float*)d_in[2];
    const float* W1 = (const float*)d_in[3];
    const float* b1 = (const float*)d_in[4];
    const float* pa = (const float*)d_in[5];
    const float* W2 = (const float*)d_in[6];
    const float* b2 = (const float*)d_in[7];
    float* OUT = (float*)d_out;

    cudaFuncSetAttribute(din_mma, cudaFuncAttributeMaxDynamicSharedMemorySize, SMEM_DYN);
    prep<<<256, 128>>>(X, W1, b1);
    din_mma<<<BB * NN / 2, 128, SMEM_DYN>>>(X, VM, W1, pa, W2, b2, OUT);
}

// round 10
// speedup vs baseline: 2.8155x; 1.0432x over previous
#include <cuda_runtime.h>
#include <cuda_bf16.h>

#define BB 8
#define NN 512
#define DD 64

typedef unsigned int u32;
typedef unsigned short u16;

#define SWZ(o)   ((o) ^ (((o) >> 3) & 0x70))   // 128B-row swizzle
#define SCSWZ(o) ((o) ^ (((o) >> 4) & 0x70))   // 256B-row swizzle (scores)

// global scratch: X split into bf16 hi/lo, swizzled tile-ready layout
__device__ char  g_xh[BB * 4 * 16384];   // [b][tile][SWZ(row*128+dp*4)]
__device__ char  g_xl[BB * 4 * 16384];
__device__ float g_hq[BB * NN * 64];     // hq + b1

// ---- dynamic smem offsets (per-CTA), single X buffer ----
#define OXH   0
#define OXL   16384
#define OSCH  32768                      // scores hi [8][256B]
#define OSCL  34816                      // scores lo [8][256B]
#define OPART 36864                      // 2q*128k*2 halves f32 = 2KB
#define OBIAS 38912                      // 2*64 f32
#define OW2   39424                      // 64 f32
#define SMEM_DYN 39680

static __device__ __forceinline__ u32 smem_u32(const void* p) {
    u32 a;
    asm("{ .reg .u64 t; cvta.to.shared.u64 t, %1; cvt.u32.u64 %0, t; }" : "=r"(a) : "l"(p));
    return a;
}
static __device__ __forceinline__ void ldsm_x4(u32* r, u32 addr) {
    asm volatile("ldmatrix.sync.aligned.m8n8.x4.shared.b16 {%0,%1,%2,%3}, [%4];"
        : "=r"(r[0]), "=r"(r[1]), "=r"(r[2]), "=r"(r[3]) : "r"(addr));
}
static __device__ __forceinline__ void ldsm_x4t(u32* r, u32 addr) {
    asm volatile("ldmatrix.sync.aligned.m8n8.x4.trans.shared.b16 {%0,%1,%2,%3}, [%4];"
        : "=r"(r[0]), "=r"(r[1]), "=r"(r[2]), "=r"(r[3]) : "r"(addr));
}
static __device__ __forceinline__ void ldsm_x2(u32* r, u32 addr) {
    asm volatile("ldmatrix.sync.aligned.m8n8.x2.shared.b16 {%0,%1}, [%2];"
        : "=r"(r[0]), "=r"(r[1]) : "r"(addr));
}
static __device__ __forceinline__ void mma_bf16(float* c, const u32* a, const u32* b) {
    asm volatile("mma.sync.aligned.m16n8k16.row.col.f32.bf16.bf16.f32 "
        "{%0,%1,%2,%3}, {%4,%5,%6,%7}, {%8,%9}, {%0,%1,%2,%3};"
        : "+f"(c[0]), "+f"(c[1]), "+f"(c[2]), "+f"(c[3])
        : "r"(a[0]), "r"(a[1]), "r"(a[2]), "r"(a[3]), "r"(b[0]), "r"(b[1]));
}
static __device__ __forceinline__ void split2(float a0, float a1, u32& hp, u32& lp) {
    __nv_bfloat16 h0 = __float2bfloat16(a0), h1 = __float2bfloat16(a1);
    __nv_bfloat16 l0 = __float2bfloat16(a0 - __bfloat162float(h0));
    __nv_bfloat16 l1 = __float2bfloat16(a1 - __bfloat162float(h1));
    hp = (u32)__bfloat16_as_ushort(h0) | ((u32)__bfloat16_as_ushort(h1) << 16);
    lp = (u32)__bfloat16_as_ushort(l0) | ((u32)__bfloat16_as_ushort(l1) << 16);
}
static __device__ __forceinline__ void cpasync16(u32 saddr, const void* gptr) {
    asm volatile("{ .reg .u64 g; cvta.to.global.u64 g, %1; "
                 "cp.async.ca.shared.global [%0], [g], 16; }"
                 :: "r"(saddr), "l"(gptr));
}
#define CP_COMMIT() asm volatile("cp.async.commit_group;" ::: "memory")
#define CP_WAIT0()  asm volatile("cp.async.wait_group 0;" ::: "memory")

// ---------------------------------------------------------------------------
// Fused prep: (a) split X rows into bf16 hi/lo swizzled tiles,
//             (b) hq[b,n,h] = x . (Wq+Wd)[h,:] + b1[h].
// ---------------------------------------------------------------------------
__global__ __launch_bounds__(128) void prep(
    const float* __restrict__ X, const float* __restrict__ W1,
    const float* __restrict__ B1)
{
    __shared__ float sx[16 * DD];
    const int tid = threadIdx.x, b = blockIdx.x >> 5, n0 = (blockIdx.x & 31) * 16;
    for (int i = tid; i < 256; i += 128)
        reinterpret_cast<float4*>(sx)[i] =
            reinterpret_cast<const float4*>(X + (b * NN + n0) * DD)[i];
    __syncthreads();

    {   // xsplit part
        const int t = n0 >> 7, rbase = n0 & 127;
        char* dh = g_xh + b * 65536 + t * 16384;
        char* dl = g_xl + b * 65536 + t * 16384;
        #pragma unroll 4
        for (int p = tid; p < 512; p += 128) {
            int r = p >> 5, dp = p & 31;
            float2 v = *(const float2*)(sx + r * DD + dp * 2);
            u32 hp, lp; split2(v.x, v.y, hp, lp);
            u32 o = SWZ((u32)((rbase + r) * 128 + dp * 4));
            *(u32*)(dh + o) = hp;
            *(u32*)(dl + o) = lp;
        }
    }
    if (tid < 64) {   // hq part, thread = h
        const float bb = __ldg(B1 + tid);
        const float4* w1row = reinterpret_cast<const float4*>(W1 + tid * 256);
        float4 w[16];
        #pragma unroll
        for (int j = 0; j < 16; j++) {
            float4 wq = __ldg(&w1row[j]);
            float4 wd = __ldg(&w1row[32 + j]);
            w[j] = make_float4(wq.x + wd.x, wq.y + wd.y, wq.z + wd.z, wq.w + wd.w);
        }
        for (int nn = 0; nn < 16; nn++) {
            const float4* xr = reinterpret_cast<const float4*>(sx + nn * DD);
            float s = 0.f;
            #pragma unroll
            for (int j = 0; j < 16; j++) {
                float4 xv = xr[j];
                s += w[j].x * xv.x + w[j].y * xv.y + w[j].z * xv.z + w[j].w * xv.w;
            }
            g_hq[(b * NN + n0 + nn) * 64 + tid] = s + bb;
        }
    }
}

// ---------------------------------------------------------------------------
// Main. One CTA = (b, queries qb, qb+1). 4 warps = 2 q x 2 h-halves.
// Single X buffer + <=128 regs -> 4 CTAs/SM; cross-CTA overlap hides the
// serialized phases. A'(q,32h) mma B-frags live in registers.
// ---------------------------------------------------------------------------
__global__ __launch_bounds__(128, 4) void din_mma(
    const float* __restrict__ X, const float* __restrict__ VM,
    const float* __restrict__ W1, const float* __restrict__ PA,
    const float* __restrict__ W2, const float* __restrict__ B2,
    float* __restrict__ OUT)
{
    extern __shared__ __align__(128) char sm[];
    const u32 smb = smem_u32(sm);

    const int tid = threadIdx.x, wid = tid >> 5, lid = tid & 31;
    const int q_w = wid >> 1, hh = wid & 1;
    const int b = blockIdx.x & 7, g = blockIdx.x >> 3;      // g 0..255
    const int qb = 2 * (255 - g);              // long queries first
    const int q_mine = qb + q_w;
    const int nt = ((qb + 1) >> 7) + 1;
    const float* Xb = X + b * NN * DD;
    float* part = (float*)(sm + OPART);

    // zero score buffers (rows 2-7 of both stay zero forever; row 4 is the
    // guaranteed-zero source for the encoded-phase x4 loads)
    for (int p = tid; p < 1024; p += 128) ((u32*)(sm + OSCH))[p] = 0;
    // bias from precomputed hq
    ((float*)(sm + OBIAS))[tid] = g_hq[(b * NN + qb + (tid >> 6)) * 64 + (tid & 63)];
    if (tid < 64) ((float*)(sm + OW2))[tid] = __ldg(W2 + tid);

    // ---- A' staging (128 rows = 2q x 64h) into X buffer, frags -> regs ----
    u32 bh[4][4][2], bl[4][4][2];
    for (int p = tid; p < 4096; p += 128) {
        int r = p >> 5, dp = p & 31, d = dp * 2;
        int q = qb + (r >> 6);
        const float* w1r = W1 + (r & 63) * 256;
        float x0 = __ldg(Xb + q * DD + d), x1 = __ldg(Xb + q * DD + d + 1);
        float a0 = fmaf(__ldg(w1r + 192 + d),     x0, __ldg(w1r + 64 + d)     - __ldg(w1r + 128 + d));
        float a1 = fmaf(__ldg(w1r + 192 + d + 1), x1, __ldg(w1r + 64 + d + 1) - __ldg(w1r + 128 + d + 1));
        u32 hp, lp; split2(a0, a1, hp, lp);
        u32 o = SWZ((u32)(r * 128 + dp * 4));
        *(u32*)(sm + OXH + o) = hp;
        *(u32*)(sm + OXL + o) = lp;
    }
    __syncthreads();
    {
        int rbase = q_w * 64 + hh * 32;
        #pragma unroll
        for (int nb = 0; nb < 4; nb++)
            #pragma unroll
            for (int ks = 0; ks < 4; ks++) {
                u32 o = SWZ((u32)((rbase + nb * 8 + (lid & 7)) * 128
                                  + ks * 32 + ((lid >> 3) & 1) * 16));
                ldsm_x2(bh[nb][ks], smb + OXH + o);
                ldsm_x2(bl[nb][ks], smb + OXL + o);
            }
    }
    __syncthreads();   // frags loaded; buffer free

    // ---- prefetch tile 0 ----
    {
        const char* sh = g_xh + b * 65536;
        const char* sl = g_xl + b * 65536;
        for (int i = tid; i < 1024; i += 128) {
            cpasync16(smb + OXH + i * 16, sh + i * 16);
            cpasync16(smb + OXL + i * 16, sl + i * 16);
        }
        CP_COMMIT();
    }

    const float aslope = __ldg(PA);
    const float b2v    = __ldg(B2);
    float ec0[4] = {0.f, 0.f, 0.f, 0.f};
    float ec1[4] = {0.f, 0.f, 0.f, 0.f};

    #pragma unroll 1
    for (int t = 0; t < nt; t++) {
        const int k0 = t << 7;
        const u32 xh_b = smb + OXH, xl_b = smb + OXL;
        CP_WAIT0();
        __syncthreads();

        // ========== S phase: warp = (q_w, 32 h of half hh) ==========
        const int mi_hi = (k0 <= q_mine) ? min(8, ((q_mine - k0) >> 4) + 1) : 0;
        #pragma unroll 1
        for (int mi = 0; mi < mi_hi; mi++) {
            u32 ah[4][4], al[4][4];
            {
                int arow  = mi * 16 + (lid & 15);
                int acolb = (lid >> 4) * 16;
                #pragma unroll
                for (int ks = 0; ks < 4; ks++) {
                    u32 o = SWZ((u32)(arow * 128 + ks * 32 + acolb));
                    ldsm_x4(ah[ks], xh_b + o);
                    ldsm_x4(al[ks], xl_b + o);
                }
            }
            float c[4][4];
            #pragma unroll
            for (int nb = 0; nb < 4; nb++)
                #pragma unroll
                for (int i = 0; i < 4; i++) c[nb][i] = 0.f;
            #pragma unroll
            for (int nb = 0; nb < 4; nb++)
                #pragma unroll
                for (int ks = 0; ks < 4; ks++) {
                    mma_bf16(c[nb], ah[ks], bh[nb][ks]);
                    mma_bf16(c[nb], ah[ks], bl[nb][ks]);
                    mma_bf16(c[nb], al[ks], bh[nb][ks]);
                }
            float s0 = 0.f, s8 = 0.f;
            #pragma unroll
            for (int nb = 0; nb < 4; nb++) {
                int hcol = hh * 32 + nb * 8 + 2 * (lid & 3);
                float2 bias2 = *(const float2*)(sm + OBIAS + (q_w * 64 + hcol) * 4);
                float2 w22   = *(const float2*)(sm + OW2 + hcol * 4);
                float v0 = c[nb][0] + bias2.x, v1 = c[nb][1] + bias2.y;
                float v2 = c[nb][2] + bias2.x, v3 = c[nb][3] + bias2.y;
                float p0 = fmaxf(v0, 0.f) + aslope * fminf(v0, 0.f);
                float p1 = fmaxf(v1, 0.f) + aslope * fminf(v1, 0.f);
                float p2 = fmaxf(v2, 0.f) + aslope * fminf(v2, 0.f);
                float p3 = fmaxf(v3, 0.f) + aslope * fminf(v3, 0.f);
                s0 = fmaf(p0, w22.x, fmaf(p1, w22.y, s0));
                s8 = fmaf(p2, w22.x, fmaf(p3, w22.y, s8));
            }
            s0 += __shfl_xor_sync(0xffffffffu, s0, 1);
            s0 += __shfl_xor_sync(0xffffffffu, s0, 2);
            s8 += __shfl_xor_sync(0xffffffffu, s8, 1);
            s8 += __shfl_xor_sync(0xffffffffu, s8, 2);
            if ((lid & 3) == 0) {
                int kr = mi * 16 + (lid >> 2);
                part[(q_w * 128 + kr) * 2 + hh]     = s0;
                part[(q_w * 128 + kr + 8) * 2 + hh] = s8;
            }
        }
        for (int mi = mi_hi; mi < 8; mi++)
            if (lid < 16) part[(q_w * 128 + mi * 16 + lid) * 2 + hh] = 0.f;
        __syncthreads();

        // ---- combine h-halves -> masked scores, split bf16 hi/lo ----
        for (int p = tid; p < 256; p += 128) {
            int q = p >> 7, kk = p & 127;
            float cm = (k0 + kk <= qb + q) ? __ldg(VM + b * NN + k0 + kk) : 0.f;
            float s = (part[(q * 128 + kk) * 2] + part[(q * 128 + kk) * 2 + 1]
                       + b2v) * cm;
            __nv_bfloat16 h = __float2bfloat16(s);
            __nv_bfloat16 l = __float2bfloat16(s - __bfloat162float(h));
            u32 o = SCSWZ((u32)(q * 256 + kk * 2));
            *(u16*)(sm + OSCH + o) = __bfloat16_as_ushort(h);
            *(u16*)(sm + OSCL + o) = __bfloat16_as_ushort(l);
        }
        __syncthreads();

        // ========== encoded mma: ec += scores . X (causally bounded) ========
        {
            const int kt_hi = min(8, ((qb + 1 - k0) >> 4) + 1);
            const int r8 = lid & 7, grp = lid >> 3;
            const u32 zoff = SCSWZ(4u * 256u);   // guaranteed-zero 16B row
            #pragma unroll 1
            for (int kt = 0; kt < kt_hi; kt++) {
                // scores A-frag: one x4 each (zero rows sourced from row 4)
                u32 soff = SCSWZ((u32)(r8 * 256 + kt * 32 + (grp >> 1) * 16));
                u32 off  = (grp & 1) ? zoff : soff;
                u32 ash[4], asl[4];
                ldsm_x4(ash, smb + OSCH + off);
                ldsm_x4(asl, smb + OSCL + off);
                // X B-frags: one x4t each for hi/lo (16 d-cols per warp)
                u32 xo = SWZ((u32)((kt * 16 + (lid & 15)) * 128
                                   + wid * 32 + (lid >> 4) * 16));
                u32 bxh[4], bxl[4];
                ldsm_x4t(bxh, xh_b + xo);
                ldsm_x4t(bxl, xl_b + xo);
                mma_bf16(ec0, ash, &bxh[0]);
                mma_bf16(ec0, ash, &bxl[0]);
                mma_bf16(ec0, asl, &bxh[0]);
                mma_bf16(ec1, ash, &bxh[2]);
                mma_bf16(ec1, ash, &bxl[2]);
                mma_bf16(ec1, asl, &bxh[2]);
            }
        }
        __syncthreads();   // buffer free for next tile's prefetch

        if (t + 1 < nt) {
            const char* sh = g_xh + b * 65536 + (t + 1) * 16384;
            const char* sl = g_xl + b * 65536 + (t + 1) * 16384;
            for (int i = tid; i < 1024; i += 128) {
                cpasync16(smb + OXH + i * 16, sh + i * 16);
                cpasync16(smb + OXL + i * 16, sl + i * 16);
            }
            CP_COMMIT();
        }
    }

    // ---- output: rows 0-1 of ec0/ec1 (lanes 0-7) ----
    if (lid < 8) {
        int q = lid >> 2, d0 = wid * 16 + 2 * (lid & 3);
        *(float2*)(OUT + (b * NN + qb + q) * DD + d0)     = make_float2(ec0[0], ec0[1]);
        *(float2*)(OUT + (b * NN + qb + q) * DD + d0 + 8) = make_float2(ec1[0], ec1[1]);
    }
}

// ---------------------------------------------------------------------------
// Inputs (metadata order):
//  0 past_lengths (unused)  1 user_embeddings [8,512,64] f32  2 valid_mask [8,512]
//  3 W1 [64,256]  4 b1 [64]  5 prelu_a [1]  6 W2 [1,64]  7 b2 [1]
// Output: encoded [8,512,64] f32
// ---------------------------------------------------------------------------
extern "C" void kernel_launch(void* const* d_in, const int* in_sizes, int n_in,
                              void* d_out, int out_size)
{
    const float* X  = (const float*)d_in[1];
    const float* VM = (const float*)d_in[2];
    const float* W1 = (const float*)d_in[3];
    const float* b1 = (const float*)d_in[4];
    const float* pa = (const float*)d_in[5];
    const float* W2 = (const float*)d_in[6];
    const float* b2 = (const float*)d_in[7];
    float* OUT = (float*)d_out;

    cudaFuncSetAttribute(din_mma, cudaFuncAttributeMaxDynamicSharedMemorySize, SMEM_DYN);
    prep<<<256, 128>>>(X, W1, b1);
    din_mma<<<BB * NN / 2, 128, SMEM_DYN>>>(X, VM, W1, pa, W2, b2, OUT);
}

// round 11
// speedup vs baseline: 2.8778x; 1.0221x over previous
#include <cuda_runtime.h>
#include <cuda_bf16.h>

#define BB 8
#define NN 512
#define DD 64

typedef unsigned int u32;
typedef unsigned short u16;

#define SWZ(o)   ((o) ^ (((o) >> 3) & 0x70))   // 128B-row swizzle
#define SCSWZ(o) ((o) ^ (((o) >> 4) & 0x70))   // 256B-row swizzle (scores)

// global scratch: X split into bf16 hi/lo, swizzled tile-ready layout
__device__ __align__(128) char  g_xh[BB * 4 * 16384];   // [b][tile][SWZ(row*128+dp*4)]
__device__ __align__(128) char  g_xl[BB * 4 * 16384];
__device__ float g_hq[BB * NN * 64];     // hq + b1

// ---- dynamic smem offsets (per-CTA), single X buffer ----
#define OXH   0
#define OXL   16384
#define OSCH  32768                      // scores hi [8][256B]
#define OSCL  34816                      // scores lo [8][256B]
#define OPART 36864                      // 2q*128k*2 halves f32 = 2KB
#define OBIAS 38912                      // 2*64 f32
#define OW2   39424                      // 64 f32
#define OMBAR 39680                      // 8B mbarrier
#define SMEM_DYN 39696

static __device__ __forceinline__ u32 smem_u32(const void* p) {
    u32 a;
    asm("{ .reg .u64 t; cvta.to.shared.u64 t, %1; cvt.u32.u64 %0, t; }" : "=r"(a) : "l"(p));
    return a;
}
static __device__ __forceinline__ void ldsm_x4(u32* r, u32 addr) {
    asm volatile("ldmatrix.sync.aligned.m8n8.x4.shared.b16 {%0,%1,%2,%3}, [%4];"
        : "=r"(r[0]), "=r"(r[1]), "=r"(r[2]), "=r"(r[3]) : "r"(addr));
}
static __device__ __forceinline__ void ldsm_x4t(u32* r, u32 addr) {
    asm volatile("ldmatrix.sync.aligned.m8n8.x4.trans.shared.b16 {%0,%1,%2,%3}, [%4];"
        : "=r"(r[0]), "=r"(r[1]), "=r"(r[2]), "=r"(r[3]) : "r"(addr));
}
static __device__ __forceinline__ void ldsm_x2(u32* r, u32 addr) {
    asm volatile("ldmatrix.sync.aligned.m8n8.x2.shared.b16 {%0,%1}, [%2];"
        : "=r"(r[0]), "=r"(r[1]) : "r"(addr));
}
static __device__ __forceinline__ void mma_bf16(float* c, const u32* a, const u32* b) {
    asm volatile("mma.sync.aligned.m16n8k16.row.col.f32.bf16.bf16.f32 "
        "{%0,%1,%2,%3}, {%4,%5,%6,%7}, {%8,%9}, {%0,%1,%2,%3};"
        : "+f"(c[0]), "+f"(c[1]), "+f"(c[2]), "+f"(c[3])
        : "r"(a[0]), "r"(a[1]), "r"(a[2]), "r"(a[3]), "r"(b[0]), "r"(b[1]));
}
static __device__ __forceinline__ void split2(float a0, float a1, u32& hp, u32& lp) {
    __nv_bfloat16 h0 = __float2bfloat16(a0), h1 = __float2bfloat16(a1);
    __nv_bfloat16 l0 = __float2bfloat16(a0 - __bfloat162float(h0));
    __nv_bfloat16 l1 = __float2bfloat16(a1 - __bfloat162float(h1));
    hp = (u32)__bfloat16_as_ushort(h0) | ((u32)__bfloat16_as_ushort(h1) << 16);
    lp = (u32)__bfloat16_as_ushort(l0) | ((u32)__bfloat16_as_ushort(l1) << 16);
}
// ---- bulk async copy (sm_90 base ISA) + mbarrier ----
static __device__ __forceinline__ void bulkcp(u32 dst, const void* src, u32 bytes, u32 mbar) {
    asm volatile("{ .reg .u64 g; cvta.to.global.u64 g, %1;\n\t"
        "cp.async.bulk.shared::cluster.global.mbarrier::complete_tx::bytes [%0], [g], %2, [%3]; }"
        :: "r"(dst), "l"(src), "r"(bytes), "r"(mbar) : "memory");
}
static __device__ __forceinline__ void mbar_expect(u32 mbar, u32 bytes) {
    asm volatile("mbarrier.arrive.expect_tx.shared.b64 _, [%0], %1;"
        :: "r"(mbar), "r"(bytes) : "memory");
}
#define MBAR_INIT(a, n) asm volatile("mbarrier.init.shared.b64 [%0], %1;" :: "r"(a), "r"(n) : "memory")
#define MBAR_WAIT(addr, ph) do { u32 _done; \
    asm volatile("{ .reg .pred p; mbarrier.try_wait.parity.acquire.cta.shared::cta.b64 p, [%1], %2; selp.b32 %0,1,0,p; }" \
        : "=r"(_done) : "r"(addr), "r"(ph) : "memory"); \
    while (!_done) { \
        asm volatile("{ .reg .pred p; mbarrier.try_wait.parity.acquire.cta.shared::cta.b64 p, [%1], %2, 0x989680; selp.b32 %0,1,0,p; }" \
            : "=r"(_done) : "r"(addr), "r"(ph) : "memory"); } } while (0)

// ---------------------------------------------------------------------------
// Fused prep: (a) split X rows into bf16 hi/lo swizzled tiles,
//             (b) hq[b,n,h] = x . (Wq+Wd)[h,:] + b1[h].
// ---------------------------------------------------------------------------
__global__ __launch_bounds__(128) void prep(
    const float* __restrict__ X, const float* __restrict__ W1,
    const float* __restrict__ B1)
{
    __shared__ float sx[16 * DD];
    const int tid = threadIdx.x, b = blockIdx.x >> 5, n0 = (blockIdx.x & 31) * 16;
    for (int i = tid; i < 256; i += 128)
        reinterpret_cast<float4*>(sx)[i] =
            reinterpret_cast<const float4*>(X + (b * NN + n0) * DD)[i];
    __syncthreads();

    {   // xsplit part
        const int t = n0 >> 7, rbase = n0 & 127;
        char* dh = g_xh + b * 65536 + t * 16384;
        char* dl = g_xl + b * 65536 + t * 16384;
        #pragma unroll 4
        for (int p = tid; p < 512; p += 128) {
            int r = p >> 5, dp = p & 31;
            float2 v = *(const float2*)(sx + r * DD + dp * 2);
            u32 hp, lp; split2(v.x, v.y, hp, lp);
            u32 o = SWZ((u32)((rbase + r) * 128 + dp * 4));
            *(u32*)(dh + o) = hp;
            *(u32*)(dl + o) = lp;
        }
    }
    if (tid < 64) {   // hq part, thread = h
        const float bb = __ldg(B1 + tid);
        const float4* w1row = reinterpret_cast<const float4*>(W1 + tid * 256);
        float4 w[16];
        #pragma unroll
        for (int j = 0; j < 16; j++) {
            float4 wq = __ldg(&w1row[j]);
            float4 wd = __ldg(&w1row[32 + j]);
            w[j] = make_float4(wq.x + wd.x, wq.y + wd.y, wq.z + wd.z, wq.w + wd.w);
        }
        for (int nn = 0; nn < 16; nn++) {
            const float4* xr = reinterpret_cast<const float4*>(sx + nn * DD);
            float s = 0.f;
            #pragma unroll
            for (int j = 0; j < 16; j++) {
                float4 xv = xr[j];
                s += w[j].x * xv.x + w[j].y * xv.y + w[j].z * xv.z + w[j].w * xv.w;
            }
            g_hq[(b * NN + n0 + nn) * 64 + tid] = s + bb;
        }
    }
}

// ---------------------------------------------------------------------------
// Main. One CTA = (b, queries qb, qb+1). 4 warps = 2 q x 2 h-halves.
// Single X buffer + <=128 regs -> 4 CTAs/SM; cross-CTA overlap hides the
// serialized phases. A'(q,32h) mma B-frags live in registers. X tiles are
// staged via cp.async.bulk (1 instr per 16KB) + mbarrier completion.
// ---------------------------------------------------------------------------
__global__ __launch_bounds__(128, 4) void din_mma(
    const float* __restrict__ X, const float* __restrict__ VM,
    const float* __restrict__ W1, const float* __restrict__ PA,
    const float* __restrict__ W2, const float* __restrict__ B2,
    float* __restrict__ OUT)
{
    extern __shared__ __align__(128) char sm[];
    const u32 smb = smem_u32(sm);
    const u32 mbar = smb + OMBAR;

    const int tid = threadIdx.x, wid = tid >> 5, lid = tid & 31;
    const int q_w = wid >> 1, hh = wid & 1;
    const int b = blockIdx.x & 7, g = blockIdx.x >> 3;      // g 0..255
    const int qb = 2 * (255 - g);              // long queries first
    const int q_mine = qb + q_w;
    const int nt = ((qb + 1) >> 7) + 1;
    const float* Xb = X + b * NN * DD;
    float* part = (float*)(sm + OPART);

    // zero score buffers (rows 2-7 of both stay zero forever; row 4 is the
    // guaranteed-zero source for the encoded-phase x4 loads)
    for (int p = tid; p < 1024; p += 128) ((u32*)(sm + OSCH))[p] = 0;
    // bias from precomputed hq
    ((float*)(sm + OBIAS))[tid] = g_hq[(b * NN + qb + (tid >> 6)) * 64 + (tid & 63)];
    if (tid < 64) ((float*)(sm + OW2))[tid] = __ldg(W2 + tid);
    if (tid == 0) MBAR_INIT(mbar, 1);

    // ---- A' staging (128 rows = 2q x 64h) into X buffer, frags -> regs ----
    u32 bh[4][4][2], bl[4][4][2];
    for (int p = tid; p < 4096; p += 128) {
        int r = p >> 5, dp = p & 31, d = dp * 2;
        int q = qb + (r >> 6);
        const float* w1r = W1 + (r & 63) * 256;
        float x0 = __ldg(Xb + q * DD + d), x1 = __ldg(Xb + q * DD + d + 1);
        float a0 = fmaf(__ldg(w1r + 192 + d),     x0, __ldg(w1r + 64 + d)     - __ldg(w1r + 128 + d));
        float a1 = fmaf(__ldg(w1r + 192 + d + 1), x1, __ldg(w1r + 64 + d + 1) - __ldg(w1r + 128 + d + 1));
        u32 hp, lp; split2(a0, a1, hp, lp);
        u32 o = SWZ((u32)(r * 128 + dp * 4));
        *(u32*)(sm + OXH + o) = hp;
        *(u32*)(sm + OXL + o) = lp;
    }
    __syncthreads();
    {
        int rbase = q_w * 64 + hh * 32;
        #pragma unroll
        for (int nb = 0; nb < 4; nb++)
            #pragma unroll
            for (int ks = 0; ks < 4; ks++) {
                u32 o = SWZ((u32)((rbase + nb * 8 + (lid & 7)) * 128
                                  + ks * 32 + ((lid >> 3) & 1) * 16));
                ldsm_x2(bh[nb][ks], smb + OXH + o);
                ldsm_x2(bl[nb][ks], smb + OXL + o);
            }
    }
    __syncthreads();   // frags loaded; buffer free, mbarrier init visible

    // ---- prefetch tile 0 (bulk) ----
    if (tid == 0) {
        mbar_expect(mbar, 32768);
        bulkcp(smb + OXH, g_xh + b * 65536, 16384, mbar);
        bulkcp(smb + OXL, g_xl + b * 65536, 16384, mbar);
    }

    const float aslope = __ldg(PA);
    const float b2v    = __ldg(B2);
    float ec0[4] = {0.f, 0.f, 0.f, 0.f};
    float ec1[4] = {0.f, 0.f, 0.f, 0.f};

    #pragma unroll 1
    for (int t = 0; t < nt; t++) {
        const int k0 = t << 7;
        const u32 xh_b = smb + OXH, xl_b = smb + OXL;
        MBAR_WAIT(mbar, t & 1);    // tile data ready (acquire)

        // ========== S phase: warp = (q_w, 32 h of half hh) ==========
        const int mi_hi = (k0 <= q_mine) ? min(8, ((q_mine - k0) >> 4) + 1) : 0;
        #pragma unroll 1
        for (int mi = 0; mi < mi_hi; mi++) {
            u32 ah[4][4], al[4][4];
            {
                int arow  = mi * 16 + (lid & 15);
                int acolb = (lid >> 4) * 16;
                #pragma unroll
                for (int ks = 0; ks < 4; ks++) {
                    u32 o = SWZ((u32)(arow * 128 + ks * 32 + acolb));
                    ldsm_x4(ah[ks], xh_b + o);
                    ldsm_x4(al[ks], xl_b + o);
                }
            }
            float c[4][4];
            #pragma unroll
            for (int nb = 0; nb < 4; nb++)
                #pragma unroll
                for (int i = 0; i < 4; i++) c[nb][i] = 0.f;
            #pragma unroll
            for (int nb = 0; nb < 4; nb++)
                #pragma unroll
                for (int ks = 0; ks < 4; ks++) {
                    mma_bf16(c[nb], ah[ks], bh[nb][ks]);
                    mma_bf16(c[nb], ah[ks], bl[nb][ks]);
                    mma_bf16(c[nb], al[ks], bh[nb][ks]);
                }
            float s0 = 0.f, s8 = 0.f;
            #pragma unroll
            for (int nb = 0; nb < 4; nb++) {
                int hcol = hh * 32 + nb * 8 + 2 * (lid & 3);
                float2 bias2 = *(const float2*)(sm + OBIAS + (q_w * 64 + hcol) * 4);
                float2 w22   = *(const float2*)(sm + OW2 + hcol * 4);
                float v0 = c[nb][0] + bias2.x, v1 = c[nb][1] + bias2.y;
                float v2 = c[nb][2] + bias2.x, v3 = c[nb][3] + bias2.y;
                float p0 = fmaxf(v0, 0.f) + aslope * fminf(v0, 0.f);
                float p1 = fmaxf(v1, 0.f) + aslope * fminf(v1, 0.f);
                float p2 = fmaxf(v2, 0.f) + aslope * fminf(v2, 0.f);
                float p3 = fmaxf(v3, 0.f) + aslope * fminf(v3, 0.f);
                s0 = fmaf(p0, w22.x, fmaf(p1, w22.y, s0));
                s8 = fmaf(p2, w22.x, fmaf(p3, w22.y, s8));
            }
            s0 += __shfl_xor_sync(0xffffffffu, s0, 1);
            s0 += __shfl_xor_sync(0xffffffffu, s0, 2);
            s8 += __shfl_xor_sync(0xffffffffu, s8, 1);
            s8 += __shfl_xor_sync(0xffffffffu, s8, 2);
            if ((lid & 3) == 0) {
                int kr = mi * 16 + (lid >> 2);
                part[(q_w * 128 + kr) * 2 + hh]     = s0;
                part[(q_w * 128 + kr + 8) * 2 + hh] = s8;
            }
        }
        for (int mi = mi_hi; mi < 8; mi++)
            if (lid < 16) part[(q_w * 128 + mi * 16 + lid) * 2 + hh] = 0.f;
        __syncthreads();

        // ---- combine h-halves -> masked scores, split bf16 hi/lo ----
        for (int p = tid; p < 256; p += 128) {
            int q = p >> 7, kk = p & 127;
            float cm = (k0 + kk <= qb + q) ? __ldg(VM + b * NN + k0 + kk) : 0.f;
            float s = (part[(q * 128 + kk) * 2] + part[(q * 128 + kk) * 2 + 1]
                       + b2v) * cm;
            __nv_bfloat16 h = __float2bfloat16(s);
            __nv_bfloat16 l = __float2bfloat16(s - __bfloat162float(h));
            u32 o = SCSWZ((u32)(q * 256 + kk * 2));
            *(u16*)(sm + OSCH + o) = __bfloat16_as_ushort(h);
            *(u16*)(sm + OSCL + o) = __bfloat16_as_ushort(l);
        }
        __syncthreads();

        // ========== encoded mma: ec += scores . X (causally bounded) ========
        {
            const int kt_hi = min(8, ((qb + 1 - k0) >> 4) + 1);
            const int r8 = lid & 7, grp = lid >> 3;
            const u32 zoff = SCSWZ(4u * 256u);   // guaranteed-zero 16B row
            #pragma unroll 1
            for (int kt = 0; kt < kt_hi; kt++) {
                // scores A-frag: one x4 each (zero rows sourced from row 4)
                u32 soff = SCSWZ((u32)(r8 * 256 + kt * 32 + (grp >> 1) * 16));
                u32 off  = (grp & 1) ? zoff : soff;
                u32 ash[4], asl[4];
                ldsm_x4(ash, smb + OSCH + off);
                ldsm_x4(asl, smb + OSCL + off);
                // X B-frags: one x4t each for hi/lo (16 d-cols per warp)
                u32 xo = SWZ((u32)((kt * 16 + (lid & 15)) * 128
                                   + wid * 32 + (lid >> 4) * 16));
                u32 bxh[4], bxl[4];
                ldsm_x4t(bxh, xh_b + xo);
                ldsm_x4t(bxl, xl_b + xo);
                mma_bf16(ec0, ash, &bxh[0]);
                mma_bf16(ec0, ash, &bxl[0]);
                mma_bf16(ec0, asl, &bxh[0]);
                mma_bf16(ec1, ash, &bxh[2]);
                mma_bf16(ec1, ash, &bxl[2]);
                mma_bf16(ec1, asl, &bxh[2]);
            }
        }
        __syncthreads();   // buffer free for next tile's prefetch

        if (t + 1 < nt && tid == 0) {
            mbar_expect(mbar, 32768);
            bulkcp(smb + OXH, g_xh + b * 65536 + (t + 1) * 16384, 16384, mbar);
            bulkcp(smb + OXL, g_xl + b * 65536 + (t + 1) * 16384, 16384, mbar);
        }
    }

    // ---- output: rows 0-1 of ec0/ec1 (lanes 0-7) ----
    if (lid < 8) {
        int q = lid >> 2, d0 = wid * 16 + 2 * (lid & 3);
        *(float2*)(OUT + (b * NN + qb + q) * DD + d0)     = make_float2(ec0[0], ec0[1]);
        *(float2*)(OUT + (b * NN + qb + q) * DD + d0 + 8) = make_float2(ec1[0], ec1[1]);
    }
}

// ---------------------------------------------------------------------------
// Inputs (metadata order):
//  0 past_lengths (unused)  1 user_embeddings [8,512,64] f32  2 valid_mask [8,512]
//  3 W1 [64,256]  4 b1 [64]  5 prelu_a [1]  6 W2 [1,64]  7 b2 [1]
// Output: encoded [8,512,64] f32
// ---------------------------------------------------------------------------
extern "C" void kernel_launch(void* const* d_in, const int* in_sizes, int n_in,
                              void* d_out, int out_size)
{
    const float* X  = (const float*)d_in[1];
    const float* VM = (const float*)d_in[2];
    const float* W1 = (const float*)d_in[3];
    const float* b1 = (const float*)d_in[4];
    const float* pa = (const float*)d_in[5];
    const float* W2 = (const float*)d_in[6];
    const float* b2 = (const float*)d_in[7];
    float* OUT = (float*)d_out;

    cudaFuncSetAttribute(din_mma, cudaFuncAttributeMaxDynamicSharedMemorySize, SMEM_DYN);
    prep<<<256, 128>>>(X, W1, b1);
    din_mma<<<BB * NN / 2, 128, SMEM_DYN>>>(X, VM, W1, pa, W2, b2, OUT);
}